// round 7
// baseline (speedup 1.0000x reference)
#include <cuda_runtime.h>
#include <cuda_bf16.h>
#include <cstdint>

#define NDRUG 100000
#define NPROT 50000
#define EDD 800000
#define EDP 600000
#define EPD 600000
#define DD 128

// smem tile geometry: bf16 [128 rows][136 cols] (stride 272B, LDSM conflict-free)
#define ASTB 272               // row stride in bytes
#define TILE_B (128 * ASTB)    // 34816 bytes per tile
#define OFF_A_HI 0
#define OFF_A_LO TILE_B
#define OFF_B_HI (2 * TILE_B)
#define OFF_B_LO (3 * TILE_B)
#define SMEM_TOTAL (4 * TILE_B)   // 139264

// ---------------- mma helpers (baseline PTX, assembles for sm_103) ----------------
__device__ __forceinline__ uint32_t smem_u32(const void* p) {
    uint32_t a;
    asm("{ .reg .u64 t; cvta.to.shared.u64 t, %1; cvt.u32.u64 %0, t; }" : "=r"(a) : "l"(p));
    return a;
}
__device__ __forceinline__ void ldsm4(uint32_t* r, uint32_t addr) {
    asm volatile("ldmatrix.sync.aligned.m8n8.x4.shared.b16 {%0,%1,%2,%3}, [%4];"
        : "=r"(r[0]), "=r"(r[1]), "=r"(r[2]), "=r"(r[3]) : "r"(addr));
}
__device__ __forceinline__ void mma16816(float* d, const uint32_t* a, uint32_t b0, uint32_t b1) {
    asm volatile("mma.sync.aligned.m16n8k16.row.col.f32.bf16.bf16.f32 "
        "{%0,%1,%2,%3}, {%4,%5,%6,%7}, {%8,%9}, {%0,%1,%2,%3};"
        : "+f"(d[0]), "+f"(d[1]), "+f"(d[2]), "+f"(d[3])
        : "r"(a[0]), "r"(a[1]), "r"(a[2]), "r"(a[3]), "r"(b0), "r"(b1));
}
__device__ __forceinline__ void split_bf(float v, __nv_bfloat16& h, __nv_bfloat16& l) {
    h = __float2bfloat16_rn(v);
    l = __float2bfloat16_rn(v - __bfloat162float(h));
}

// ---------------- scratch ----------------
__device__ __align__(16) float g_Hdd[(size_t)NDRUG * DD];
__device__ __align__(16) float g_Hdp[(size_t)NDRUG * DD];
__device__ __align__(16) float g_Hpd[(size_t)NPROT * DD];
__device__ __align__(16) float g_Adrug[(size_t)NDRUG * DD];
__device__ __align__(16) float g_Aprot[(size_t)NPROT * DD];
// CSR
__device__ __align__(16) int g_cnt_dd[NDRUG];
__device__ __align__(16) int g_cnt_pd[NDRUG];
__device__ __align__(16) int g_cnt_dp[NPROT];
__device__ __align__(16) int g_off_dd[NDRUG + 4];
__device__ __align__(16) int g_off_pd[NDRUG + 4];
__device__ __align__(16) int g_off_dp[NPROT + 4];
__device__ __align__(16) int g_cur_dd[NDRUG + 4];
__device__ __align__(16) int g_cur_pd[NDRUG + 4];
__device__ __align__(16) int g_cur_dp[NPROT + 4];
__device__ int g_esrc_dd[EDD];
__device__ int g_esrc_pd[EPD];
__device__ int g_esrc_dp[EDP];
// bf16 split weights, [n][k] row-major
__device__ __align__(16) __nv_bfloat16 g_WAdd_hi[DD * DD];
__device__ __align__(16) __nv_bfloat16 g_WAdd_lo[DD * DD];
__device__ __align__(16) __nv_bfloat16 g_WAdp_hi[DD * DD];
__device__ __align__(16) __nv_bfloat16 g_WAdp_lo[DD * DD];
__device__ __align__(16) __nv_bfloat16 g_WApd_hi[DD * DD];
__device__ __align__(16) __nv_bfloat16 g_WApd_lo[DD * DD];
__device__ __align__(16) __nv_bfloat16 g_WNdr_hi[DD * 2 * DD];
__device__ __align__(16) __nv_bfloat16 g_WNdr_lo[DD * 2 * DD];
__device__ __align__(16) __nv_bfloat16 g_WNpr_hi[DD * 2 * DD];
__device__ __align__(16) __nv_bfloat16 g_WNpr_lo[DD * 2 * DD];

// ---------------- CSR build ----------------
__global__ void zero_counts() {
    int t = blockIdx.x * blockDim.x + threadIdx.x;
    int stride = gridDim.x * blockDim.x;
    for (int i = t; i < NDRUG; i += stride) { g_cnt_dd[i] = 0; g_cnt_pd[i] = 0; }
    for (int i = t; i < NPROT; i += stride) g_cnt_dp[i] = 0;
}

__global__ void count_edges(const int* __restrict__ dst, int* __restrict__ cnt, int E) {
    int t = blockIdx.x * blockDim.x + threadIdx.x;
    if (t < E) atomicAdd(&cnt[__ldg(&dst[t])], 1);
}

__global__ __launch_bounds__(1024, 1) void scan_counts() {
    const int* cnt; int* offs; int* cur; int n;
    if (blockIdx.x == 0)      { cnt = g_cnt_dd; offs = g_off_dd; cur = g_cur_dd; n = NDRUG; }
    else if (blockIdx.x == 1) { cnt = g_cnt_pd; offs = g_off_pd; cur = g_cur_pd; n = NDRUG; }
    else                      { cnt = g_cnt_dp; offs = g_off_dp; cur = g_cur_dp; n = NPROT; }
    __shared__ int wsum[32];
    __shared__ int carry_s;
    int tid = threadIdx.x, lane = tid & 31, wid = tid >> 5;
    if (tid == 0) carry_s = 0;
    __syncthreads();
    for (int base = 0; base < n; base += 4096) {
        int i0 = base + tid * 4;
        int4 c = make_int4(0, 0, 0, 0);
        if (i0 < n) c = *reinterpret_cast<const int4*>(&cnt[i0]);
        int tot = c.x + c.y + c.z + c.w;
        int incl = tot;
#pragma unroll
        for (int o = 1; o < 32; o <<= 1) {
            int v = __shfl_up_sync(0xFFFFFFFFu, incl, o);
            if (lane >= o) incl += v;
        }
        if (lane == 31) wsum[wid] = incl;
        __syncthreads();
        if (wid == 0) {
            int v = wsum[lane];
            int wincl = v;
#pragma unroll
            for (int o = 1; o < 32; o <<= 1) {
                int t2 = __shfl_up_sync(0xFFFFFFFFu, wincl, o);
                if (lane >= o) wincl += t2;
            }
            wsum[lane] = wincl - v;
        }
        __syncthreads();
        int excl = carry_s + wsum[wid] + incl - tot;
        if (i0 < n) {
            int e0 = excl, e1 = e0 + c.x, e2 = e1 + c.y, e3 = e2 + c.z;
            *reinterpret_cast<int4*>(&offs[i0]) = make_int4(e0, e1, e2, e3);
            *reinterpret_cast<int4*>(&cur[i0])  = make_int4(e0, e1, e2, e3);
        }
        __syncthreads();
        if (tid == 1023) carry_s = excl + tot;
        __syncthreads();
    }
    if (tid == 0) offs[n] = carry_s;
}

__global__ void fill_edges(const int* __restrict__ src, const int* __restrict__ dst,
                           int* __restrict__ cur, int* __restrict__ esrc, int E) {
    int t = blockIdx.x * blockDim.x + threadIdx.x;
    if (t < E) {
        int d = __ldg(&dst[t]);
        int slot = atomicAdd(&cur[d], 1);
        esrc[slot] = __ldg(&src[t]);
    }
}

// ---------------- weight prep: split fp32 -> bf16 hi/lo, [n][k] row-major ----------------
__global__ void prep_weights(const float* __restrict__ Wdd, const float* __restrict__ Wdp,
                             const float* __restrict__ Wpd, const float* __restrict__ Wdr,
                             const float* __restrict__ Wpr)
{
    int t = blockIdx.x * blockDim.x + threadIdx.x;
    int stride = gridDim.x * blockDim.x;
    for (int i = t; i < DD * DD; i += stride) {
        __nv_bfloat16 h, l;
        split_bf(Wdd[i], h, l); g_WAdd_hi[i] = h; g_WAdd_lo[i] = l;
        split_bf(Wdp[i], h, l); g_WAdp_hi[i] = h; g_WAdp_lo[i] = l;
        split_bf(Wpd[i], h, l); g_WApd_hi[i] = h; g_WApd_lo[i] = l;
    }
    for (int i = t; i < DD * 2 * DD; i += stride) {
        __nv_bfloat16 h, l;
        split_bf(Wdr[i], h, l); g_WNdr_hi[i] = h; g_WNdr_lo[i] = l;
        split_bf(Wpr[i], h, l); g_WNpr_hi[i] = h; g_WNpr_lo[i] = l;
    }
}

// ---------------- shared device helpers for staging ----------------
// Stage fp32 source rows [row0..row0+128) x 128 cols as bf16 hi/lo smem tiles.
__device__ __forceinline__ void stage_A_split(
    unsigned char* smem, const float* __restrict__ X, int row0, int N, int tid)
{
    const float4* Xv = reinterpret_cast<const float4*>(X);
    for (int j = tid; j < 2048; j += 256) {
        int r = j >> 4, kc = j & 15;
        int row = row0 + r;
        float4 f0 = make_float4(0.f, 0.f, 0.f, 0.f);
        float4 f1 = f0;
        if (row < N) {
            f0 = Xv[(size_t)row * 32 + kc * 2];
            f1 = Xv[(size_t)row * 32 + kc * 2 + 1];
        }
        float f[8] = {f0.x, f0.y, f0.z, f0.w, f1.x, f1.y, f1.z, f1.w};
        uint32_t hw[4], lw[4];
#pragma unroll
        for (int q = 0; q < 4; q++) {
            __nv_bfloat16 h0, l0, h1, l1;
            split_bf(f[2 * q], h0, l0);
            split_bf(f[2 * q + 1], h1, l1);
            hw[q] = (uint32_t)__bfloat16_as_ushort(h0) | ((uint32_t)__bfloat16_as_ushort(h1) << 16);
            lw[q] = (uint32_t)__bfloat16_as_ushort(l0) | ((uint32_t)__bfloat16_as_ushort(l1) << 16);
        }
        *reinterpret_cast<uint4*>(smem + OFF_A_HI + r * ASTB + kc * 16) = make_uint4(hw[0], hw[1], hw[2], hw[3]);
        *reinterpret_cast<uint4*>(smem + OFF_A_LO + r * ASTB + kc * 16) = make_uint4(lw[0], lw[1], lw[2], lw[3]);
    }
}

// Copy pre-split bf16 weights [128 n][128 k slice] into B smem tiles.
// src rows have row_stride_u4 uint4 per row; slice starts at col_u4 offset.
__device__ __forceinline__ void stage_B(
    unsigned char* smem, const uint4* __restrict__ Whi, const uint4* __restrict__ Wlo,
    int row_stride_u4, int col_u4, int tid)
{
    for (int j = tid; j < 2048; j += 256) {
        int r = j >> 4, kc = j & 15;
        *reinterpret_cast<uint4*>(smem + OFF_B_HI + r * ASTB + kc * 16) = Whi[r * row_stride_u4 + col_u4 + kc];
        *reinterpret_cast<uint4*>(smem + OFF_B_LO + r * ASTB + kc * 16) = Wlo[r * row_stride_u4 + col_u4 + kc];
    }
}

// One K=128 pass set: C += Ahi*Bhi + Ahi*Blo + Alo*Bhi  (split-bf16)
__device__ __forceinline__ void mma_passes(
    uint32_t sb, float (*C)[4], int w, int lane)
{
    int lr = lane & 15, lc = lane >> 4;
    uint32_t a_row_off = (uint32_t)((w * 16 + lr) * ASTB + lc * 16);
    uint32_t b_lane_off = (uint32_t)(lr * ASTB + lc * 16);
#pragma unroll
    for (int p = 0; p < 3; p++) {
        uint32_t abase = sb + (p == 2 ? OFF_A_LO : OFF_A_HI) + a_row_off;
        uint32_t bbase = sb + (p == 1 ? OFF_B_LO : OFF_B_HI) + b_lane_off;
#pragma unroll
        for (int ks = 0; ks < 8; ks++) {
            uint32_t a[4];
            ldsm4(a, abase + ks * 32);
#pragma unroll
            for (int pr = 0; pr < 8; pr++) {
                uint32_t b[4];
                ldsm4(b, bbase + pr * 16 * ASTB + ks * 32);
                mma16816(C[2 * pr],     a, b[0], b[2]);
                mma16816(C[2 * pr + 1], a, b[1], b[3]);
            }
        }
    }
}

// Write C frags to smem stage [128][132] floats at given base, optional relu.
__device__ __forceinline__ void stage_C(
    float* hs, float (*C)[4], int w, int lane, bool relu)
{
    int g = lane >> 2, q = lane & 3;
#pragma unroll
    for (int pr = 0; pr < 16; pr++) {
        int col = pr * 8 + 2 * q;
        float2 v0 = make_float2(C[pr][0], C[pr][1]);
        float2 v1 = make_float2(C[pr][2], C[pr][3]);
        if (relu) {
            v0.x = fmaxf(v0.x, 0.f); v0.y = fmaxf(v0.y, 0.f);
            v1.x = fmaxf(v1.x, 0.f); v1.y = fmaxf(v1.y, 0.f);
        }
        *reinterpret_cast<float2*>(&hs[(w * 16 + g) * 132 + col])     = v0;
        *reinterpret_cast<float2*>(&hs[(w * 16 + g + 8) * 132 + col]) = v1;
    }
}

// ---------------- agg GEMM: H = relu(X @ W^T), tensor cores ----------------
__global__ __launch_bounds__(256, 1) void agg_mma(
    const float* __restrict__ X,
    const uint4* __restrict__ Whi, const uint4* __restrict__ Wlo,
    float* __restrict__ H, int N)
{
    extern __shared__ __align__(16) unsigned char smem[];
    uint32_t sb = smem_u32(smem);
    int tid = threadIdx.x, w = tid >> 5, lane = tid & 31;
    int row0 = blockIdx.x * 128;

    stage_A_split(smem, X, row0, N, tid);
    stage_B(smem, Whi, Wlo, 16, 0, tid);
    __syncthreads();

    float C[16][4];
#pragma unroll
    for (int i = 0; i < 16; i++)
#pragma unroll
        for (int j = 0; j < 4; j++) C[i][j] = 0.f;

    mma_passes(sb, C, w, lane);
    __syncthreads();  // done reading smem -> reuse as stage

    float* hs = reinterpret_cast<float*>(smem);
    stage_C(hs, C, w, lane, true);
    __syncthreads();

    // coalesced store: warp w writes rows w*16 .. +16, lane covers 4 cols
    for (int r = 0; r < 16; r++) {
        int rl = w * 16 + r;
        int row = row0 + rl;
        if (row < N) {
            float4 v = *reinterpret_cast<float4*>(&hs[rl * 132 + lane * 4]);
            *reinterpret_cast<float4*>(&H[(size_t)row * DD + lane * 4]) = v;
        }
    }
}

// ---------------- node update: relu([x,a]@W^T + b) + x -> LN ----------------
__global__ __launch_bounds__(256, 1) void node_mma(
    const float* __restrict__ X,
    const float* __restrict__ A,
    const uint4* __restrict__ Whi, const uint4* __restrict__ Wlo,  // [128][256] bf16
    const float* __restrict__ b,
    const float* __restrict__ g,
    const float* __restrict__ be,
    float* __restrict__ out, int N)
{
    extern __shared__ __align__(16) unsigned char smem[];
    uint32_t sb = smem_u32(smem);
    int tid = threadIdx.x, w = tid >> 5, lane = tid & 31;
    int row0 = blockIdx.x * 128;

    float C[16][4];
#pragma unroll
    for (int i = 0; i < 16; i++)
#pragma unroll
        for (int j = 0; j < 4; j++) C[i][j] = 0.f;

    // phase 0: self half (X, W[:, :128])
    stage_A_split(smem, X, row0, N, tid);
    stage_B(smem, Whi, Wlo, 32, 0, tid);
    __syncthreads();
    mma_passes(sb, C, w, lane);
    __syncthreads();

    // phase 1: agg half (A, W[:, 128:])
    stage_A_split(smem, A, row0, N, tid);
    stage_B(smem, Whi, Wlo, 32, 16, tid);
    __syncthreads();
    mma_passes(sb, C, w, lane);
    __syncthreads();

    float* hs = reinterpret_cast<float*>(smem);
    stage_C(hs, C, w, lane, false);
    __syncthreads();

    // epilogue: bias + relu + residual + LayerNorm; warp w owns rows w*16..+16
    float4 bb  = *reinterpret_cast<const float4*>(&b[lane * 4]);
    float4 gg  = *reinterpret_cast<const float4*>(&g[lane * 4]);
    float4 bev = *reinterpret_cast<const float4*>(&be[lane * 4]);
    for (int r = 0; r < 16; r++) {
        int rl = w * 16 + r;
        int row = row0 + rl;
        float4 v = *reinterpret_cast<float4*>(&hs[rl * 132 + lane * 4]);
        float4 xr = make_float4(0.f, 0.f, 0.f, 0.f);
        if (row < N) xr = *reinterpret_cast<const float4*>(&X[(size_t)row * DD + lane * 4]);
        v.x = fmaxf(v.x + bb.x, 0.f) + xr.x;
        v.y = fmaxf(v.y + bb.y, 0.f) + xr.y;
        v.z = fmaxf(v.z + bb.z, 0.f) + xr.z;
        v.w = fmaxf(v.w + bb.w, 0.f) + xr.w;
        float s  = v.x + v.y + v.z + v.w;
        float s2 = v.x * v.x + v.y * v.y + v.z * v.z + v.w * v.w;
#pragma unroll
        for (int o_ = 16; o_; o_ >>= 1) {
            s  += __shfl_xor_sync(0xFFFFFFFFu, s, o_);
            s2 += __shfl_xor_sync(0xFFFFFFFFu, s2, o_);
        }
        float mu  = s * (1.0f / 128.0f);
        float var = s2 * (1.0f / 128.0f) - mu * mu;
        float rstd = rsqrtf(var + 1e-5f);
        if (row < N) {
            float4 o;
            o.x = (v.x - mu) * rstd * gg.x + bev.x;
            o.y = (v.y - mu) * rstd * gg.y + bev.y;
            o.z = (v.z - mu) * rstd * gg.z + bev.z;
            o.w = (v.w - mu) * rstd * gg.w + bev.w;
            *reinterpret_cast<float4*>(&out[(size_t)row * DD + lane * 4]) = o;
        }
    }
}

// ---------------- CSR gather ----------------
__global__ __launch_bounds__(256) void edge_gather(
    const float* __restrict__ H, const int* __restrict__ esrc,
    const int* __restrict__ offs, float* __restrict__ A, int N, int mode)
{
    int w = (blockIdx.x * blockDim.x + threadIdx.x) >> 5;
    if (w >= N) return;
    int lane = threadIdx.x & 31;
    int beg = __ldg(&offs[w]), end = __ldg(&offs[w + 1]);
    float4 acc = make_float4(0.f, 0.f, 0.f, 0.f);
    int e = beg;
    for (; e + 4 <= end; e += 4) {
        int s0 = __ldg(&esrc[e]);
        int s1 = __ldg(&esrc[e + 1]);
        int s2 = __ldg(&esrc[e + 2]);
        int s3 = __ldg(&esrc[e + 3]);
        float4 v0 = __ldg(reinterpret_cast<const float4*>(&H[(size_t)s0 * DD + lane * 4]));
        float4 v1 = __ldg(reinterpret_cast<const float4*>(&H[(size_t)s1 * DD + lane * 4]));
        float4 v2 = __ldg(reinterpret_cast<const float4*>(&H[(size_t)s2 * DD + lane * 4]));
        float4 v3 = __ldg(reinterpret_cast<const float4*>(&H[(size_t)s3 * DD + lane * 4]));
        acc.x += (v0.x + v1.x) + (v2.x + v3.x);
        acc.y += (v0.y + v1.y) + (v2.y + v3.y);
        acc.z += (v0.z + v1.z) + (v2.z + v3.z);
        acc.w += (v0.w + v1.w) + (v2.w + v3.w);
    }
    for (; e < end; e++) {
        int s = __ldg(&esrc[e]);
        float4 v = __ldg(reinterpret_cast<const float4*>(&H[(size_t)s * DD + lane * 4]));
        acc.x += v.x; acc.y += v.y; acc.z += v.z; acc.w += v.w;
    }
    float inv = 1.0f / fmaxf((float)(end - beg), 1.0f);
    float4 o = make_float4(acc.x * inv, acc.y * inv, acc.z * inv, acc.w * inv);
    float* p = &A[(size_t)w * DD + lane * 4];
    if (mode) {
        float4 prev = *reinterpret_cast<const float4*>(p);
        o.x = 0.5f * (prev.x + o.x);
        o.y = 0.5f * (prev.y + o.y);
        o.z = 0.5f * (prev.z + o.z);
        o.w = 0.5f * (prev.w + o.w);
    }
    *reinterpret_cast<float4*>(p) = o;
}

// ---------------- launch ----------------
extern "C" void kernel_launch(void* const* d_in, const int* in_sizes, int n_in,
                              void* d_out, int out_size)
{
    const float* x_drug  = (const float*)d_in[0];
    const float* x_prot  = (const float*)d_in[1];
    const float* Wagg_dd = (const float*)d_in[2];
    const float* Wagg_dp = (const float*)d_in[3];
    const float* Wagg_pd = (const float*)d_in[4];
    const float* W_drug  = (const float*)d_in[5];
    const float* b_drug  = (const float*)d_in[6];
    const float* W_prot  = (const float*)d_in[7];
    const float* b_prot  = (const float*)d_in[8];
    const float* g_drug  = (const float*)d_in[9];
    const float* be_drug = (const float*)d_in[10];
    const float* g_prot  = (const float*)d_in[11];
    const float* be_prot = (const float*)d_in[12];
    const int* dd_src = (const int*)d_in[13];
    const int* dd_dst = (const int*)d_in[14];
    const int* dp_src = (const int*)d_in[15];
    const int* dp_dst = (const int*)d_in[16];
    const int* pd_src = (const int*)d_in[17];
    const int* pd_dst = (const int*)d_in[18];
    float* out = (float*)d_out;

    float *Hdd, *Hdp, *Hpd, *Adrug, *Aprot;
    int *cnt_dd, *cnt_pd, *cnt_dp, *off_dd, *off_pd, *off_dp;
    int *cur_dd, *cur_pd, *cur_dp, *esrc_dd, *esrc_pd, *esrc_dp;
    uint4 *WAdd_hi, *WAdd_lo, *WAdp_hi, *WAdp_lo, *WApd_hi, *WApd_lo;
    uint4 *WNdr_hi, *WNdr_lo, *WNpr_hi, *WNpr_lo;
    cudaGetSymbolAddress((void**)&Hdd, g_Hdd);
    cudaGetSymbolAddress((void**)&Hdp, g_Hdp);
    cudaGetSymbolAddress((void**)&Hpd, g_Hpd);
    cudaGetSymbolAddress((void**)&Adrug, g_Adrug);
    cudaGetSymbolAddress((void**)&Aprot, g_Aprot);
    cudaGetSymbolAddress((void**)&cnt_dd, g_cnt_dd);
    cudaGetSymbolAddress((void**)&cnt_pd, g_cnt_pd);
    cudaGetSymbolAddress((void**)&cnt_dp, g_cnt_dp);
    cudaGetSymbolAddress((void**)&off_dd, g_off_dd);
    cudaGetSymbolAddress((void**)&off_pd, g_off_pd);
    cudaGetSymbolAddress((void**)&off_dp, g_off_dp);
    cudaGetSymbolAddress((void**)&cur_dd, g_cur_dd);
    cudaGetSymbolAddress((void**)&cur_pd, g_cur_pd);
    cudaGetSymbolAddress((void**)&cur_dp, g_cur_dp);
    cudaGetSymbolAddress((void**)&esrc_dd, g_esrc_dd);
    cudaGetSymbolAddress((void**)&esrc_pd, g_esrc_pd);
    cudaGetSymbolAddress((void**)&esrc_dp, g_esrc_dp);
    cudaGetSymbolAddress((void**)&WAdd_hi, g_WAdd_hi);
    cudaGetSymbolAddress((void**)&WAdd_lo, g_WAdd_lo);
    cudaGetSymbolAddress((void**)&WAdp_hi, g_WAdp_hi);
    cudaGetSymbolAddress((void**)&WAdp_lo, g_WAdp_lo);
    cudaGetSymbolAddress((void**)&WApd_hi, g_WApd_hi);
    cudaGetSymbolAddress((void**)&WApd_lo, g_WApd_lo);
    cudaGetSymbolAddress((void**)&WNdr_hi, g_WNdr_hi);
    cudaGetSymbolAddress((void**)&WNdr_lo, g_WNdr_lo);
    cudaGetSymbolAddress((void**)&WNpr_hi, g_WNpr_hi);
    cudaGetSymbolAddress((void**)&WNpr_lo, g_WNpr_lo);

    cudaFuncSetAttribute(agg_mma,  cudaFuncAttributeMaxDynamicSharedMemorySize, SMEM_TOTAL);
    cudaFuncSetAttribute(node_mma, cudaFuncAttributeMaxDynamicSharedMemorySize, SMEM_TOTAL);

    // CSR build + weight prep
    zero_counts<<<256, 256>>>();
    prep_weights<<<256, 256>>>(Wagg_dd, Wagg_dp, Wagg_pd, W_drug, W_prot);
    count_edges<<<(EDD + 255) / 256, 256>>>(dd_dst, cnt_dd, EDD);
    count_edges<<<(EPD + 255) / 256, 256>>>(pd_dst, cnt_pd, EPD);
    count_edges<<<(EDP + 255) / 256, 256>>>(dp_dst, cnt_dp, EDP);
    scan_counts<<<3, 1024>>>();
    fill_edges<<<(EDD + 255) / 256, 256>>>(dd_src, dd_dst, cur_dd, esrc_dd, EDD);
    fill_edges<<<(EPD + 255) / 256, 256>>>(pd_src, pd_dst, cur_pd, esrc_pd, EPD);
    fill_edges<<<(EDP + 255) / 256, 256>>>(dp_src, dp_dst, cur_dp, esrc_dp, EDP);

    // tensor-core GEMMs + gathers, interleaved for L2 residency
    int gb_drug = (NDRUG + 127) / 128;
    int gb_prot = (NPROT + 127) / 128;
    agg_mma<<<gb_drug, 256, SMEM_TOTAL>>>(x_drug, WAdd_hi, WAdd_lo, Hdd, NDRUG);
    edge_gather<<<(NDRUG * 32 + 255) / 256, 256>>>(Hdd, esrc_dd, off_dd, Adrug, NDRUG, 0);

    agg_mma<<<gb_prot, 256, SMEM_TOTAL>>>(x_prot, WApd_hi, WApd_lo, Hpd, NPROT);
    edge_gather<<<(NDRUG * 32 + 255) / 256, 256>>>(Hpd, esrc_pd, off_pd, Adrug, NDRUG, 1);

    agg_mma<<<gb_drug, 256, SMEM_TOTAL>>>(x_drug, WAdp_hi, WAdp_lo, Hdp, NDRUG);
    edge_gather<<<(NPROT * 32 + 255) / 256, 256>>>(Hdp, esrc_dp, off_dp, Aprot, NPROT, 0);

    node_mma<<<gb_drug, 256, SMEM_TOTAL>>>(
        x_drug, Adrug, WNdr_hi, WNdr_lo, b_drug, g_drug, be_drug, out, NDRUG);
    node_mma<<<gb_prot, 256, SMEM_TOTAL>>>(
        x_prot, Aprot, WNpr_hi, WNpr_lo, b_prot, g_prot, be_prot,
        out + (size_t)NDRUG * DD, NPROT);
}

// round 8
// speedup vs baseline: 1.0049x; 1.0049x over previous
#include <cuda_runtime.h>
#include <cstdint>

#define NDRUG 100000
#define NPROT 50000
#define EDD 800000
#define EDP 600000
#define EPD 600000
#define DD 128
#define XP 34    // u64 stride per k-row in packed-pair tiles (32 pairs + 2 pad)

typedef unsigned long long u64;

__device__ __forceinline__ u64 pk2(float lo, float hi) {
    u64 r; asm("mov.b64 %0,{%1,%2};" : "=l"(r) : "f"(lo), "f"(hi)); return r;
}
__device__ __forceinline__ void fma2(u64& d, u64 a, u64 b) {
    asm("fma.rn.f32x2 %0,%1,%2,%3;" : "=l"(d) : "l"(a), "l"(b), "l"(d));
}
__device__ __forceinline__ void up2(u64 v, float& lo, float& hi) {
    asm("mov.b64 {%0,%1},%2;" : "=f"(lo), "=f"(hi) : "l"(v));
}

// ---------------- scratch ----------------
__device__ __align__(16) float g_Hdd[(size_t)NDRUG * DD];
__device__ __align__(16) float g_Hdp[(size_t)NDRUG * DD];
__device__ __align__(16) float g_Hpd[(size_t)NPROT * DD];
__device__ __align__(16) float g_Adrug[(size_t)NDRUG * DD];
__device__ __align__(16) float g_Aprot[(size_t)NPROT * DD];
// CSR
__device__ __align__(16) int g_cnt_dd[NDRUG];
__device__ __align__(16) int g_cnt_pd[NDRUG];
__device__ __align__(16) int g_cnt_dp[NPROT];
__device__ __align__(16) int g_off_dd[NDRUG + 4];
__device__ __align__(16) int g_off_pd[NDRUG + 4];
__device__ __align__(16) int g_off_dp[NPROT + 4];
__device__ __align__(16) int g_cur_dd[NDRUG + 4];
__device__ __align__(16) int g_cur_pd[NDRUG + 4];
__device__ __align__(16) int g_cur_dp[NPROT + 4];
__device__ int g_esrc_dd[EDD];
__device__ int g_esrc_pd[EPD];
__device__ int g_esrc_dp[EDP];
// duplicated-pair weights: Wd[k*stride + c] = (w,w) where w = W[c][k]
__device__ __align__(16) u64 g_WdDD[DD * DD];
__device__ __align__(16) u64 g_WdDP[DD * DD];
__device__ __align__(16) u64 g_WdPD[DD * DD];
__device__ __align__(16) u64 g_WdDR[DD * 2 * DD];
__device__ __align__(16) u64 g_WdPR[DD * 2 * DD];

// ---------------- CSR build ----------------
__global__ void zero_counts() {
    int t = blockIdx.x * blockDim.x + threadIdx.x;
    int stride = gridDim.x * blockDim.x;
    for (int i = t; i < NDRUG; i += stride) { g_cnt_dd[i] = 0; g_cnt_pd[i] = 0; }
    for (int i = t; i < NPROT; i += stride) g_cnt_dp[i] = 0;
}

__global__ void count_all(const int* __restrict__ dd, const int* __restrict__ pd,
                          const int* __restrict__ dp) {
    int t = blockIdx.x * blockDim.x + threadIdx.x;
    if (t < EDD) atomicAdd(&g_cnt_dd[__ldg(&dd[t])], 1);
    else if (t < EDD + EPD) atomicAdd(&g_cnt_pd[__ldg(&pd[t - EDD])], 1);
    else if (t < EDD + EPD + EDP) atomicAdd(&g_cnt_dp[__ldg(&dp[t - EDD - EPD])], 1);
}

__global__ __launch_bounds__(1024, 1) void scan_counts() {
    const int* cnt; int* offs; int* cur; int n;
    if (blockIdx.x == 0)      { cnt = g_cnt_dd; offs = g_off_dd; cur = g_cur_dd; n = NDRUG; }
    else if (blockIdx.x == 1) { cnt = g_cnt_pd; offs = g_off_pd; cur = g_cur_pd; n = NDRUG; }
    else                      { cnt = g_cnt_dp; offs = g_off_dp; cur = g_cur_dp; n = NPROT; }
    __shared__ int wsum[32];
    __shared__ int carry_s;
    int tid = threadIdx.x, lane = tid & 31, wid = tid >> 5;
    if (tid == 0) carry_s = 0;
    __syncthreads();
    for (int base = 0; base < n; base += 4096) {
        int i0 = base + tid * 4;
        int4 c = make_int4(0, 0, 0, 0);
        if (i0 < n) c = *reinterpret_cast<const int4*>(&cnt[i0]);
        int tot = c.x + c.y + c.z + c.w;
        int incl = tot;
#pragma unroll
        for (int o = 1; o < 32; o <<= 1) {
            int v = __shfl_up_sync(0xFFFFFFFFu, incl, o);
            if (lane >= o) incl += v;
        }
        if (lane == 31) wsum[wid] = incl;
        __syncthreads();
        if (wid == 0) {
            int v = wsum[lane];
            int wincl = v;
#pragma unroll
            for (int o = 1; o < 32; o <<= 1) {
                int t2 = __shfl_up_sync(0xFFFFFFFFu, wincl, o);
                if (lane >= o) wincl += t2;
            }
            wsum[lane] = wincl - v;
        }
        __syncthreads();
        int excl = carry_s + wsum[wid] + incl - tot;
        if (i0 < n) {
            int e0 = excl, e1 = e0 + c.x, e2 = e1 + c.y, e3 = e2 + c.z;
            *reinterpret_cast<int4*>(&offs[i0]) = make_int4(e0, e1, e2, e3);
            *reinterpret_cast<int4*>(&cur[i0])  = make_int4(e0, e1, e2, e3);
        }
        __syncthreads();
        if (tid == 1023) carry_s = excl + tot;
        __syncthreads();
    }
    if (tid == 0) offs[n] = carry_s;
}

__global__ void fill_all(const int* __restrict__ dd_s, const int* __restrict__ dd_d,
                         const int* __restrict__ pd_s, const int* __restrict__ pd_d,
                         const int* __restrict__ dp_s, const int* __restrict__ dp_d) {
    int t = blockIdx.x * blockDim.x + threadIdx.x;
    if (t < EDD) {
        int slot = atomicAdd(&g_cur_dd[__ldg(&dd_d[t])], 1);
        g_esrc_dd[slot] = __ldg(&dd_s[t]);
    } else if (t < EDD + EPD) {
        int e = t - EDD;
        int slot = atomicAdd(&g_cur_pd[__ldg(&pd_d[e])], 1);
        g_esrc_pd[slot] = __ldg(&pd_s[e]);
    } else if (t < EDD + EPD + EDP) {
        int e = t - EDD - EPD;
        int slot = atomicAdd(&g_cur_dp[__ldg(&dp_d[e])], 1);
        g_esrc_dp[slot] = __ldg(&dp_s[e]);
    }
}

// ---------------- weight prep: transpose + duplicate into u64 pairs ----------------
__global__ void prep_weights(const float* __restrict__ Wdd, const float* __restrict__ Wdp,
                             const float* __restrict__ Wpd, const float* __restrict__ Wdr,
                             const float* __restrict__ Wpr)
{
    int t = blockIdx.x * blockDim.x + threadIdx.x;
    int stride = gridDim.x * blockDim.x;
    for (int i = t; i < DD * DD; i += stride) {
        int c = i >> 7, k = i & 127;
        g_WdDD[k * DD + c] = pk2(Wdd[i], Wdd[i]);
        g_WdDP[k * DD + c] = pk2(Wdp[i], Wdp[i]);
        g_WdPD[k * DD + c] = pk2(Wpd[i], Wpd[i]);
    }
    for (int i = t; i < DD * 2 * DD; i += stride) {
        int c = i >> 8, col = i & 255;
        int k = col & 127, half = col >> 7;
        g_WdDR[k * 256 + half * 128 + c] = pk2(Wdr[i], Wdr[i]);
        g_WdPR[k * 256 + half * 128 + c] = pk2(Wpr[i], Wpr[i]);
    }
}

// ---------------- agg GEMM + ReLU (f32x2, packed pairs, dup-W) ----------------
// Block: 128 threads (4 warps), tile 64 rows x 128 cols.
// Warp w: row-pairs w*8..w*8+8 (16 rows); lane: cols lane*4..+4.
__global__ __launch_bounds__(128, 4) void agg_gemm(
    const float* __restrict__ X, const u64* __restrict__ Wd,
    float* __restrict__ H, int N)
{
    __shared__ u64 xt[DD * XP];   // xt[k*XP + rp] = (X[row0+2rp][k], X[row0+2rp+1][k])

    int tid = threadIdx.x;
    int row0 = blockIdx.x * 64;
    const float4* Xv = reinterpret_cast<const float4*>(X);
    for (int j = tid; j < 1024; j += 128) {
        int rp = j & 31, kc = j >> 5;   // kc: 4-k chunk 0..31
        int ra = row0 + 2 * rp;
        float4 va = make_float4(0.f, 0.f, 0.f, 0.f);
        float4 vb = va;
        if (ra < N)     va = Xv[(size_t)ra * 32 + kc];
        if (ra + 1 < N) vb = Xv[(size_t)(ra + 1) * 32 + kc];
        xt[(kc * 4 + 0) * XP + rp] = pk2(va.x, vb.x);
        xt[(kc * 4 + 1) * XP + rp] = pk2(va.y, vb.y);
        xt[(kc * 4 + 2) * XP + rp] = pk2(va.z, vb.z);
        xt[(kc * 4 + 3) * XP + rp] = pk2(va.w, vb.w);
    }
    __syncthreads();

    int lane = tid & 31, w = tid >> 5;
    int c0 = lane * 4, p0 = w * 8;
    u64 acc[8][4];
#pragma unroll
    for (int rp = 0; rp < 8; rp++)
#pragma unroll
        for (int c = 0; c < 4; c++) acc[rp][c] = 0ull;

#pragma unroll 2
    for (int k = 0; k < DD; k++) {
        const ulonglong2* xr = reinterpret_cast<const ulonglong2*>(&xt[k * XP + p0]);
        ulonglong2 x01 = xr[0], x23 = xr[1], x45 = xr[2], x67 = xr[3];
        const ulonglong2* wr = reinterpret_cast<const ulonglong2*>(&Wd[(size_t)k * DD + c0]);
        ulonglong2 w01 = wr[0], w23 = wr[1];
        u64 xp[8] = {x01.x, x01.y, x23.x, x23.y, x45.x, x45.y, x67.x, x67.y};
        u64 wd[4] = {w01.x, w01.y, w23.x, w23.y};
#pragma unroll
        for (int rp = 0; rp < 8; rp++)
#pragma unroll
            for (int c = 0; c < 4; c++) fma2(acc[rp][c], xp[rp], wd[c]);
    }

#pragma unroll
    for (int rp = 0; rp < 8; rp++) {
        float lo[4], hi[4];
#pragma unroll
        for (int c = 0; c < 4; c++) up2(acc[rp][c], lo[c], hi[c]);
        int ra = row0 + 2 * (p0 + rp);
        if (ra < N) {
            float4 o = make_float4(fmaxf(lo[0], 0.f), fmaxf(lo[1], 0.f),
                                   fmaxf(lo[2], 0.f), fmaxf(lo[3], 0.f));
            *reinterpret_cast<float4*>(&H[(size_t)ra * DD + c0]) = o;
        }
        if (ra + 1 < N) {
            float4 o = make_float4(fmaxf(hi[0], 0.f), fmaxf(hi[1], 0.f),
                                   fmaxf(hi[2], 0.f), fmaxf(hi[3], 0.f));
            *reinterpret_cast<float4*>(&H[(size_t)(ra + 1) * DD + c0]) = o;
        }
    }
}

// ---------------- CSR gather ----------------
__global__ __launch_bounds__(256) void edge_gather(
    const float* __restrict__ H, const int* __restrict__ esrc,
    const int* __restrict__ offs, float* __restrict__ A, int N, int mode)
{
    int w = (blockIdx.x * blockDim.x + threadIdx.x) >> 5;
    if (w >= N) return;
    int lane = threadIdx.x & 31;
    int beg = __ldg(&offs[w]), end = __ldg(&offs[w + 1]);
    float4 acc = make_float4(0.f, 0.f, 0.f, 0.f);
    int e = beg;
    for (; e + 4 <= end; e += 4) {
        int s0 = __ldg(&esrc[e]);
        int s1 = __ldg(&esrc[e + 1]);
        int s2 = __ldg(&esrc[e + 2]);
        int s3 = __ldg(&esrc[e + 3]);
        float4 v0 = __ldg(reinterpret_cast<const float4*>(&H[(size_t)s0 * DD + lane * 4]));
        float4 v1 = __ldg(reinterpret_cast<const float4*>(&H[(size_t)s1 * DD + lane * 4]));
        float4 v2 = __ldg(reinterpret_cast<const float4*>(&H[(size_t)s2 * DD + lane * 4]));
        float4 v3 = __ldg(reinterpret_cast<const float4*>(&H[(size_t)s3 * DD + lane * 4]));
        acc.x += (v0.x + v1.x) + (v2.x + v3.x);
        acc.y += (v0.y + v1.y) + (v2.y + v3.y);
        acc.z += (v0.z + v1.z) + (v2.z + v3.z);
        acc.w += (v0.w + v1.w) + (v2.w + v3.w);
    }
    for (; e < end; e++) {
        int s = __ldg(&esrc[e]);
        float4 v = __ldg(reinterpret_cast<const float4*>(&H[(size_t)s * DD + lane * 4]));
        acc.x += v.x; acc.y += v.y; acc.z += v.z; acc.w += v.w;
    }
    float inv = 1.0f / fmaxf((float)(end - beg), 1.0f);
    float4 o = make_float4(acc.x * inv, acc.y * inv, acc.z * inv, acc.w * inv);
    float* p = &A[(size_t)w * DD + lane * 4];
    if (mode) {
        float4 prev = *reinterpret_cast<const float4*>(p);
        o.x = 0.5f * (prev.x + o.x);
        o.y = 0.5f * (prev.y + o.y);
        o.z = 0.5f * (prev.z + o.z);
        o.w = 0.5f * (prev.w + o.w);
    }
    *reinterpret_cast<float4*>(p) = o;
}

// ---------------- node update (f32x2 dual GEMM, packed pairs, dup-W) ----------------
// Block: 256 threads (8 warps), tile 64 rows. Warp w: row-pairs w*4..+4 (8 rows).
__global__ __launch_bounds__(256, 2) void node_update(
    const float* __restrict__ X,
    const float* __restrict__ A,
    const u64* __restrict__ Wd,   // [128][256] dup-pairs, halves packed
    const float* __restrict__ b,
    const float* __restrict__ g,
    const float* __restrict__ be,
    float* __restrict__ out, int N)
{
    __shared__ u64 xt[DD * XP];
    __shared__ u64 at[DD * XP];

    int tid = threadIdx.x;
    int row0 = blockIdx.x * 64;
    const float4* Xv = reinterpret_cast<const float4*>(X);
    const float4* Av = reinterpret_cast<const float4*>(A);
    for (int j = tid; j < 1024; j += 256) {
        int rp = j & 31, kc = j >> 5;
        int ra = row0 + 2 * rp;
        float4 xa = make_float4(0.f, 0.f, 0.f, 0.f), xb = xa, aa = xa, ab = xa;
        if (ra < N)     { xa = Xv[(size_t)ra * 32 + kc];       aa = Av[(size_t)ra * 32 + kc]; }
        if (ra + 1 < N) { xb = Xv[(size_t)(ra + 1) * 32 + kc]; ab = Av[(size_t)(ra + 1) * 32 + kc]; }
        xt[(kc * 4 + 0) * XP + rp] = pk2(xa.x, xb.x);
        xt[(kc * 4 + 1) * XP + rp] = pk2(xa.y, xb.y);
        xt[(kc * 4 + 2) * XP + rp] = pk2(xa.z, xb.z);
        xt[(kc * 4 + 3) * XP + rp] = pk2(xa.w, xb.w);
        at[(kc * 4 + 0) * XP + rp] = pk2(aa.x, ab.x);
        at[(kc * 4 + 1) * XP + rp] = pk2(aa.y, ab.y);
        at[(kc * 4 + 2) * XP + rp] = pk2(aa.z, ab.z);
        at[(kc * 4 + 3) * XP + rp] = pk2(aa.w, ab.w);
    }
    __syncthreads();

    int lane = tid & 31, w = tid >> 5;
    int c0 = lane * 4, p0 = w * 4;
    u64 acc[4][4];
#pragma unroll
    for (int rp = 0; rp < 4; rp++)
#pragma unroll
        for (int c = 0; c < 4; c++) acc[rp][c] = 0ull;

#pragma unroll 2
    for (int k = 0; k < DD; k++) {
        const ulonglong2* xr = reinterpret_cast<const ulonglong2*>(&xt[k * XP + p0]);
        const ulonglong2* ar = reinterpret_cast<const ulonglong2*>(&at[k * XP + p0]);
        ulonglong2 x01 = xr[0], x23 = xr[1];
        ulonglong2 a01 = ar[0], a23 = ar[1];
        const ulonglong2* w1r = reinterpret_cast<const ulonglong2*>(&Wd[(size_t)k * 256 + c0]);
        const ulonglong2* w2r = reinterpret_cast<const ulonglong2*>(&Wd[(size_t)k * 256 + 128 + c0]);
        ulonglong2 w1a = w1r[0], w1b = w1r[1];
        ulonglong2 w2a = w2r[0], w2b = w2r[1];
        u64 xp[4] = {x01.x, x01.y, x23.x, x23.y};
        u64 ap[4] = {a01.x, a01.y, a23.x, a23.y};
        u64 w1d[4] = {w1a.x, w1a.y, w1b.x, w1b.y};
        u64 w2d[4] = {w2a.x, w2a.y, w2b.x, w2b.y};
#pragma unroll
        for (int rp = 0; rp < 4; rp++)
#pragma unroll
            for (int c = 0; c < 4; c++) {
                fma2(acc[rp][c], xp[rp], w1d[c]);
                fma2(acc[rp][c], ap[rp], w2d[c]);
            }
    }
    float4 bb = *reinterpret_cast<const float4*>(&b[c0]);
    __syncthreads();   // done reading xt/at -> reuse xt as fp32 stage
    float* hs = reinterpret_cast<float*>(xt);   // 64x132 floats = 33.8KB <= 34.8KB

#pragma unroll
    for (int rp = 0; rp < 4; rp++) {
        float lo[4], hi[4];
#pragma unroll
        for (int c = 0; c < 4; c++) up2(acc[rp][c], lo[c], hi[c]);
        int rla = 2 * (p0 + rp);
        int ra = row0 + rla;
        float4 xra = make_float4(0.f, 0.f, 0.f, 0.f);
        float4 xrb = make_float4(0.f, 0.f, 0.f, 0.f);
        if (ra < N)     xra = *reinterpret_cast<const float4*>(&X[(size_t)ra * DD + c0]);
        if (ra + 1 < N) xrb = *reinterpret_cast<const float4*>(&X[(size_t)(ra + 1) * DD + c0]);
        float4 oa, ob;
        oa.x = fmaxf(lo[0] + bb.x, 0.f) + xra.x;
        oa.y = fmaxf(lo[1] + bb.y, 0.f) + xra.y;
        oa.z = fmaxf(lo[2] + bb.z, 0.f) + xra.z;
        oa.w = fmaxf(lo[3] + bb.w, 0.f) + xra.w;
        ob.x = fmaxf(hi[0] + bb.x, 0.f) + xrb.x;
        ob.y = fmaxf(hi[1] + bb.y, 0.f) + xrb.y;
        ob.z = fmaxf(hi[2] + bb.z, 0.f) + xrb.z;
        ob.w = fmaxf(hi[3] + bb.w, 0.f) + xrb.w;
        *reinterpret_cast<float4*>(&hs[rla * 132 + c0]) = oa;
        *reinterpret_cast<float4*>(&hs[(rla + 1) * 132 + c0]) = ob;
    }
    __syncthreads();

    // LayerNorm: warp w handles rows w*8 .. w*8+8; lane covers 4 columns
    float4 gg  = *reinterpret_cast<const float4*>(&g[lane * 4]);
    float4 bev = *reinterpret_cast<const float4*>(&be[lane * 4]);
    for (int r = 0; r < 8; r++) {
        int rl = w * 8 + r;
        int row = row0 + rl;
        float4 v = *reinterpret_cast<const float4*>(&hs[rl * 132 + lane * 4]);
        float s  = v.x + v.y + v.z + v.w;
        float s2 = v.x * v.x + v.y * v.y + v.z * v.z + v.w * v.w;
#pragma unroll
        for (int o_ = 16; o_; o_ >>= 1) {
            s  += __shfl_xor_sync(0xFFFFFFFFu, s, o_);
            s2 += __shfl_xor_sync(0xFFFFFFFFu, s2, o_);
        }
        float mu  = s * (1.0f / 128.0f);
        float var = s2 * (1.0f / 128.0f) - mu * mu;
        float rstd = rsqrtf(var + 1e-5f);
        if (row < N) {
            float4 o;
            o.x = (v.x - mu) * rstd * gg.x + bev.x;
            o.y = (v.y - mu) * rstd * gg.y + bev.y;
            o.z = (v.z - mu) * rstd * gg.z + bev.z;
            o.w = (v.w - mu) * rstd * gg.w + bev.w;
            *reinterpret_cast<float4*>(&out[(size_t)row * DD + lane * 4]) = o;
        }
    }
}

// ---------------- launch ----------------
extern "C" void kernel_launch(void* const* d_in, const int* in_sizes, int n_in,
                              void* d_out, int out_size)
{
    const float* x_drug  = (const float*)d_in[0];
    const float* x_prot  = (const float*)d_in[1];
    const float* Wagg_dd = (const float*)d_in[2];
    const float* Wagg_dp = (const float*)d_in[3];
    const float* Wagg_pd = (const float*)d_in[4];
    const float* W_drug  = (const float*)d_in[5];
    const float* b_drug  = (const float*)d_in[6];
    const float* W_prot  = (const float*)d_in[7];
    const float* b_prot  = (const float*)d_in[8];
    const float* g_drug  = (const float*)d_in[9];
    const float* be_drug = (const float*)d_in[10];
    const float* g_prot  = (const float*)d_in[11];
    const float* be_prot = (const float*)d_in[12];
    const int* dd_src = (const int*)d_in[13];
    const int* dd_dst = (const int*)d_in[14];
    const int* dp_src = (const int*)d_in[15];
    const int* dp_dst = (const int*)d_in[16];
    const int* pd_src = (const int*)d_in[17];
    const int* pd_dst = (const int*)d_in[18];
    float* out = (float*)d_out;

    float *Hdd, *Hdp, *Hpd, *Adrug, *Aprot;
    u64 *WdDD, *WdDP, *WdPD, *WdDR, *WdPR;
    int *off_dd, *off_pd, *off_dp, *esrc_dd, *esrc_pd, *esrc_dp;
    cudaGetSymbolAddress((void**)&Hdd, g_Hdd);
    cudaGetSymbolAddress((void**)&Hdp, g_Hdp);
    cudaGetSymbolAddress((void**)&Hpd, g_Hpd);
    cudaGetSymbolAddress((void**)&Adrug, g_Adrug);
    cudaGetSymbolAddress((void**)&Aprot, g_Aprot);
    cudaGetSymbolAddress((void**)&WdDD, g_WdDD);
    cudaGetSymbolAddress((void**)&WdDP, g_WdDP);
    cudaGetSymbolAddress((void**)&WdPD, g_WdPD);
    cudaGetSymbolAddress((void**)&WdDR, g_WdDR);
    cudaGetSymbolAddress((void**)&WdPR, g_WdPR);
    cudaGetSymbolAddress((void**)&off_dd, g_off_dd);
    cudaGetSymbolAddress((void**)&off_pd, g_off_pd);
    cudaGetSymbolAddress((void**)&off_dp, g_off_dp);
    cudaGetSymbolAddress((void**)&esrc_dd, g_esrc_dd);
    cudaGetSymbolAddress((void**)&esrc_pd, g_esrc_pd);
    cudaGetSymbolAddress((void**)&esrc_dp, g_esrc_dp);

    // CSR build + weight prep
    zero_counts<<<256, 256>>>();
    prep_weights<<<256, 256>>>(Wagg_dd, Wagg_dp, Wagg_pd, W_drug, W_prot);
    count_all<<<(EDD + EPD + EDP + 255) / 256, 256>>>(dd_dst, pd_dst, dp_dst);
    scan_counts<<<3, 1024>>>();
    fill_all<<<(EDD + EPD + EDP + 255) / 256, 256>>>(dd_src, dd_dst, pd_src, pd_dst, dp_src, dp_dst);

    // GEMMs + gathers, interleaved for L2 residency
    agg_gemm<<<(NDRUG + 63) / 64, 128>>>(x_drug, WdDD, Hdd, NDRUG);
    edge_gather<<<(NDRUG * 32 + 255) / 256, 256>>>(Hdd, esrc_dd, off_dd, Adrug, NDRUG, 0);

    agg_gemm<<<(NPROT + 63) / 64, 128>>>(x_prot, WdPD, Hpd, NPROT);
    edge_gather<<<(NDRUG * 32 + 255) / 256, 256>>>(Hpd, esrc_pd, off_pd, Adrug, NDRUG, 1);

    agg_gemm<<<(NDRUG + 63) / 64, 128>>>(x_drug, WdDP, Hdp, NDRUG);
    edge_gather<<<(NPROT * 32 + 255) / 256, 256>>>(Hdp, esrc_dp, off_dp, Aprot, NPROT, 0);

    node_update<<<(NDRUG + 63) / 64, 256>>>(
        x_drug, Adrug, WdDR, b_drug, g_drug, be_drug, out, NDRUG);
    node_update<<<(NPROT + 63) / 64, 256>>>(
        x_prot, Aprot, WdPR, b_prot, g_prot, be_prot,
        out + (size_t)NDRUG * DD, NPROT);
}

// round 9
// speedup vs baseline: 1.3925x; 1.3857x over previous
#include <cuda_runtime.h>
#include <cstdint>

#define NDRUG 100000
#define NPROT 50000
#define EDD 800000
#define EDP 600000
#define EPD 600000
#define DD 128
#define XTS 68

// chunked scan geometry
#define CH 4096
#define NCH_DD 25   // ceil(100000/4096)
#define NCH_PD 25
#define NCH_DP 13
#define NCH_TOT (NCH_DD + NCH_PD + NCH_DP)   // 63

typedef unsigned long long u64;

__device__ __forceinline__ u64 pk2(float lo, float hi) {
    u64 r; asm("mov.b64 %0,{%1,%2};" : "=l"(r) : "f"(lo), "f"(hi)); return r;
}
__device__ __forceinline__ u64 dp2(float v) {
    u64 r; asm("mov.b64 %0,{%1,%1};" : "=l"(r) : "f"(v)); return r;
}
__device__ __forceinline__ void fma2(u64& d, u64 a, u64 b) {
    asm("fma.rn.f32x2 %0,%1,%2,%3;" : "=l"(d) : "l"(a), "l"(b), "l"(d));
}
__device__ __forceinline__ void up2(u64 v, float& lo, float& hi) {
    asm("mov.b64 {%0,%1},%2;" : "=f"(lo), "=f"(hi) : "l"(v));
}

// ---------------- scratch ----------------
__device__ __align__(16) float g_Hdd[(size_t)NDRUG * DD];
__device__ __align__(16) float g_Hdp[(size_t)NDRUG * DD];
__device__ __align__(16) float g_Hpd[(size_t)NPROT * DD];
__device__ __align__(16) float g_Adrug[(size_t)NDRUG * DD];
__device__ __align__(16) float g_Aprot[(size_t)NPROT * DD];
// CSR
__device__ __align__(16) int g_cnt_dd[NDRUG];
__device__ __align__(16) int g_cnt_pd[NDRUG];
__device__ __align__(16) int g_cnt_dp[NPROT];
__device__ __align__(16) int g_off_dd[NDRUG + 4];
__device__ __align__(16) int g_off_pd[NDRUG + 4];
__device__ __align__(16) int g_off_dp[NPROT + 4];
__device__ __align__(16) int g_cur_dd[NDRUG + 4];
__device__ __align__(16) int g_cur_pd[NDRUG + 4];
__device__ __align__(16) int g_cur_dp[NPROT + 4];
__device__ int g_esrc_dd[EDD];
__device__ int g_esrc_pd[EPD];
__device__ int g_esrc_dp[EDP];
__device__ int g_part[NCH_TOT];
__device__ int g_pbase[NCH_TOT];
// transposed weights: Wt[k*128 + c] = W[c*128 + k]
__device__ __align__(16) float g_WtDD[DD * DD];
__device__ __align__(16) float g_WtDP[DD * DD];
__device__ __align__(16) float g_WtPD[DD * DD];
// node weights: Wt[k*256 + half*128 + c] = W[c*256 + half*128 + k]
__device__ __align__(16) float g_WtDR[DD * 2 * DD];
__device__ __align__(16) float g_WtPR[DD * 2 * DD];

// ---------------- init: zero counts + transpose weights ----------------
__global__ void init_all(const float* __restrict__ Wdd, const float* __restrict__ Wdp,
                         const float* __restrict__ Wpd, const float* __restrict__ Wdr,
                         const float* __restrict__ Wpr)
{
    int t = blockIdx.x * blockDim.x + threadIdx.x;
    int stride = gridDim.x * blockDim.x;
    for (int i = t; i < NDRUG; i += stride) { g_cnt_dd[i] = 0; g_cnt_pd[i] = 0; }
    for (int i = t; i < NPROT; i += stride) g_cnt_dp[i] = 0;
    for (int i = t; i < DD * DD; i += stride) {
        int c = i >> 7, k = i & 127;
        g_WtDD[k * DD + c] = Wdd[i];
        g_WtDP[k * DD + c] = Wdp[i];
        g_WtPD[k * DD + c] = Wpd[i];
    }
    for (int i = t; i < DD * 2 * DD; i += stride) {
        int c = i >> 8, col = i & 255;
        int k = col & 127, half = col >> 7;
        g_WtDR[k * 256 + half * 128 + c] = Wdr[i];
        g_WtPR[k * 256 + half * 128 + c] = Wpr[i];
    }
}

// ---------------- CSR build ----------------
__global__ void count_all(const int* __restrict__ dd, const int* __restrict__ pd,
                          const int* __restrict__ dp) {
    int t = blockIdx.x * blockDim.x + threadIdx.x;
    if (t < EDD) atomicAdd(&g_cnt_dd[__ldg(&dd[t])], 1);
    else if (t < EDD + EPD) atomicAdd(&g_cnt_pd[__ldg(&pd[t - EDD])], 1);
    else if (t < EDD + EPD + EDP) atomicAdd(&g_cnt_dp[__ldg(&dp[t - EDD - EPD])], 1);
}

__device__ __forceinline__ void chunk_map(int b, const int*& cnt, int*& offs, int*& cur,
                                          int& base, int& n) {
    if (b < NCH_DD)              { cnt = g_cnt_dd; offs = g_off_dd; cur = g_cur_dd; base = b * CH; n = NDRUG; }
    else if (b < NCH_DD + NCH_PD){ cnt = g_cnt_pd; offs = g_off_pd; cur = g_cur_pd; base = (b - NCH_DD) * CH; n = NDRUG; }
    else                         { cnt = g_cnt_dp; offs = g_off_dp; cur = g_cur_dp; base = (b - NCH_DD - NCH_PD) * CH; n = NPROT; }
}

__global__ __launch_bounds__(1024) void chunk_sums() {
    const int* cnt; int* offs; int* cur; int base, n;
    chunk_map(blockIdx.x, cnt, offs, cur, base, n);
    int i0 = base + threadIdx.x * 4;
    int4 c = make_int4(0, 0, 0, 0);
    if (i0 < n) c = *reinterpret_cast<const int4*>(&cnt[i0]);
    int tot = c.x + c.y + c.z + c.w;
    __shared__ int ws[32];
    int lane = threadIdx.x & 31, wid = threadIdx.x >> 5;
#pragma unroll
    for (int o = 16; o; o >>= 1) tot += __shfl_xor_sync(0xFFFFFFFFu, tot, o);
    if (lane == 0) ws[wid] = tot;
    __syncthreads();
    if (wid == 0) {
        int v = ws[lane];
#pragma unroll
        for (int o = 16; o; o >>= 1) v += __shfl_xor_sync(0xFFFFFFFFu, v, o);
        if (lane == 0) g_part[blockIdx.x] = v;
    }
}

__global__ void scan_partials() {
    __shared__ int s[64];
    int t = threadIdx.x;   // 64 threads
    int v = (t < NCH_TOT) ? g_part[t] : 0;
    s[t] = v;
    __syncthreads();
#pragma unroll
    for (int o = 1; o < 64; o <<= 1) {
        int add = (t >= o) ? s[t - o] : 0;
        __syncthreads();
        s[t] += add;
        __syncthreads();
    }
    if (t < NCH_TOT) {
        int excl = s[t] - v;
        int segoff = (t >= NCH_DD + NCH_PD) ? (EDD + EPD) : (t >= NCH_DD ? EDD : 0);
        g_pbase[t] = excl - segoff;
    }
    if (t == 0) {
        g_off_dd[NDRUG] = EDD;
        g_off_pd[NDRUG] = EPD;
        g_off_dp[NPROT] = EDP;
    }
}

__global__ __launch_bounds__(1024) void chunk_scan() {
    const int* cnt; int* offs; int* cur; int base, n;
    chunk_map(blockIdx.x, cnt, offs, cur, base, n);
    int carry = g_pbase[blockIdx.x];
    __shared__ int wsum[32];
    int tid = threadIdx.x, lane = tid & 31, wid = tid >> 5;
    int i0 = base + tid * 4;
    int4 c = make_int4(0, 0, 0, 0);
    if (i0 < n) c = *reinterpret_cast<const int4*>(&cnt[i0]);
    int tot = c.x + c.y + c.z + c.w;
    int incl = tot;
#pragma unroll
    for (int o = 1; o < 32; o <<= 1) {
        int v = __shfl_up_sync(0xFFFFFFFFu, incl, o);
        if (lane >= o) incl += v;
    }
    if (lane == 31) wsum[wid] = incl;
    __syncthreads();
    if (wid == 0) {
        int v = wsum[lane];
        int wincl = v;
#pragma unroll
        for (int o = 1; o < 32; o <<= 1) {
            int t2 = __shfl_up_sync(0xFFFFFFFFu, wincl, o);
            if (lane >= o) wincl += t2;
        }
        wsum[lane] = wincl - v;
    }
    __syncthreads();
    int excl = carry + wsum[wid] + incl - tot;
    if (i0 < n) {
        int e0 = excl, e1 = e0 + c.x, e2 = e1 + c.y, e3 = e2 + c.z;
        *reinterpret_cast<int4*>(&offs[i0]) = make_int4(e0, e1, e2, e3);
        *reinterpret_cast<int4*>(&cur[i0])  = make_int4(e0, e1, e2, e3);
    }
}

__global__ void fill_all(const int* __restrict__ dd_s, const int* __restrict__ dd_d,
                         const int* __restrict__ pd_s, const int* __restrict__ pd_d,
                         const int* __restrict__ dp_s, const int* __restrict__ dp_d) {
    int t = blockIdx.x * blockDim.x + threadIdx.x;
    if (t < EDD) {
        int slot = atomicAdd(&g_cur_dd[__ldg(&dd_d[t])], 1);
        g_esrc_dd[slot] = __ldg(&dd_s[t]);
    } else if (t < EDD + EPD) {
        int e = t - EDD;
        int slot = atomicAdd(&g_cur_pd[__ldg(&pd_d[e])], 1);
        g_esrc_pd[slot] = __ldg(&pd_s[e]);
    } else if (t < EDD + EPD + EDP) {
        int e = t - EDD - EPD;
        int slot = atomicAdd(&g_cur_dp[__ldg(&dp_d[e])], 1);
        g_esrc_dp[slot] = __ldg(&dp_s[e]);
    }
}

// ---------------- GEMM + ReLU (f32x2, W via L1-cached LDG) — proven R4 version ----------------
__global__ __launch_bounds__(256, 3) void agg_gemm_relu(
    const float* __restrict__ X, const float* __restrict__ Wt,
    float* __restrict__ H, int N)
{
    __shared__ float xt[DD * XTS];

    int tid = threadIdx.x;
    int row0 = blockIdx.x * 64;
    for (int j = tid; j < 64 * 32; j += 256) {
        int r = j & 63, qg = j >> 6;
        int row = row0 + r;
        float4 v = make_float4(0.f, 0.f, 0.f, 0.f);
        if (row < N) v = *reinterpret_cast<const float4*>(&X[(size_t)row * DD + qg * 4]);
        xt[(qg * 4 + 0) * XTS + r] = v.x;
        xt[(qg * 4 + 1) * XTS + r] = v.y;
        xt[(qg * 4 + 2) * XTS + r] = v.z;
        xt[(qg * 4 + 3) * XTS + r] = v.w;
    }
    __syncthreads();

    int ct = tid & 31, rt = tid >> 5;
    int c0 = ct * 4, r0 = rt * 8;
    u64 acc[4][4];
#pragma unroll
    for (int rp = 0; rp < 4; rp++)
#pragma unroll
        for (int c = 0; c < 4; c++) acc[rp][c] = 0ull;

#pragma unroll 4
    for (int k = 0; k < DD; k++) {
        float4 w = __ldg(reinterpret_cast<const float4*>(&Wt[k * DD + c0]));
        float4 xa = *reinterpret_cast<const float4*>(&xt[k * XTS + r0]);
        float4 xb = *reinterpret_cast<const float4*>(&xt[k * XTS + r0 + 4]);
        u64 xp[4] = {pk2(xa.x, xa.y), pk2(xa.z, xa.w), pk2(xb.x, xb.y), pk2(xb.z, xb.w)};
        u64 wd[4] = {dp2(w.x), dp2(w.y), dp2(w.z), dp2(w.w)};
#pragma unroll
        for (int rp = 0; rp < 4; rp++)
#pragma unroll
            for (int c = 0; c < 4; c++) fma2(acc[rp][c], xp[rp], wd[c]);
    }

#pragma unroll
    for (int rp = 0; rp < 4; rp++) {
        float lo[4], hi[4];
#pragma unroll
        for (int c = 0; c < 4; c++) up2(acc[rp][c], lo[c], hi[c]);
        int ra = row0 + r0 + 2 * rp;
        if (ra < N) {
            float4 o = make_float4(fmaxf(lo[0], 0.f), fmaxf(lo[1], 0.f),
                                   fmaxf(lo[2], 0.f), fmaxf(lo[3], 0.f));
            *reinterpret_cast<float4*>(&H[(size_t)ra * DD + c0]) = o;
        }
        if (ra + 1 < N) {
            float4 o = make_float4(fmaxf(hi[0], 0.f), fmaxf(hi[1], 0.f),
                                   fmaxf(hi[2], 0.f), fmaxf(hi[3], 0.f));
            *reinterpret_cast<float4*>(&H[(size_t)(ra + 1) * DD + c0]) = o;
        }
    }
}

// ---------------- CSR gather — proven R4 version ----------------
__global__ __launch_bounds__(256) void edge_gather(
    const float* __restrict__ H, const int* __restrict__ esrc,
    const int* __restrict__ offs, float* __restrict__ A, int N, int mode)
{
    int w = (blockIdx.x * blockDim.x + threadIdx.x) >> 5;
    if (w >= N) return;
    int lane = threadIdx.x & 31;
    int beg = __ldg(&offs[w]), end = __ldg(&offs[w + 1]);
    float4 acc = make_float4(0.f, 0.f, 0.f, 0.f);
    int e = beg;
    for (; e + 4 <= end; e += 4) {
        int s0 = __ldg(&esrc[e]);
        int s1 = __ldg(&esrc[e + 1]);
        int s2 = __ldg(&esrc[e + 2]);
        int s3 = __ldg(&esrc[e + 3]);
        float4 v0 = __ldg(reinterpret_cast<const float4*>(&H[(size_t)s0 * DD + lane * 4]));
        float4 v1 = __ldg(reinterpret_cast<const float4*>(&H[(size_t)s1 * DD + lane * 4]));
        float4 v2 = __ldg(reinterpret_cast<const float4*>(&H[(size_t)s2 * DD + lane * 4]));
        float4 v3 = __ldg(reinterpret_cast<const float4*>(&H[(size_t)s3 * DD + lane * 4]));
        acc.x += (v0.x + v1.x) + (v2.x + v3.x);
        acc.y += (v0.y + v1.y) + (v2.y + v3.y);
        acc.z += (v0.z + v1.z) + (v2.z + v3.z);
        acc.w += (v0.w + v1.w) + (v2.w + v3.w);
    }
    for (; e < end; e++) {
        int s = __ldg(&esrc[e]);
        float4 v = __ldg(reinterpret_cast<const float4*>(&H[(size_t)s * DD + lane * 4]));
        acc.x += v.x; acc.y += v.y; acc.z += v.z; acc.w += v.w;
    }
    float inv = 1.0f / fmaxf((float)(end - beg), 1.0f);
    float4 o = make_float4(acc.x * inv, acc.y * inv, acc.z * inv, acc.w * inv);
    float* p = &A[(size_t)w * DD + lane * 4];
    if (mode) {
        float4 prev = *reinterpret_cast<const float4*>(p);
        o.x = 0.5f * (prev.x + o.x);
        o.y = 0.5f * (prev.y + o.y);
        o.z = 0.5f * (prev.z + o.z);
        o.w = 0.5f * (prev.w + o.w);
    }
    *reinterpret_cast<float4*>(p) = o;
}

// ---------------- fused node update — proven R4 version ----------------
__global__ __launch_bounds__(256, 2) void node_update(
    const float* __restrict__ X,
    const float* __restrict__ A,
    const float* __restrict__ Wt,
    const float* __restrict__ b,
    const float* __restrict__ g,
    const float* __restrict__ be,
    float* __restrict__ out, int N)
{
    __shared__ float xt[DD * XTS];
    __shared__ float at[DD * XTS];

    int tid = threadIdx.x;
    int row0 = blockIdx.x * 64;
    for (int j = tid; j < 64 * 32; j += 256) {
        int r = j & 63, qg = j >> 6;
        int row = row0 + r;
        float4 xv = make_float4(0.f, 0.f, 0.f, 0.f);
        float4 av = make_float4(0.f, 0.f, 0.f, 0.f);
        if (row < N) {
            xv = *reinterpret_cast<const float4*>(&X[(size_t)row * DD + qg * 4]);
            av = *reinterpret_cast<const float4*>(&A[(size_t)row * DD + qg * 4]);
        }
        xt[(qg * 4 + 0) * XTS + r] = xv.x;
        xt[(qg * 4 + 1) * XTS + r] = xv.y;
        xt[(qg * 4 + 2) * XTS + r] = xv.z;
        xt[(qg * 4 + 3) * XTS + r] = xv.w;
        at[(qg * 4 + 0) * XTS + r] = av.x;
        at[(qg * 4 + 1) * XTS + r] = av.y;
        at[(qg * 4 + 2) * XTS + r] = av.z;
        at[(qg * 4 + 3) * XTS + r] = av.w;
    }
    __syncthreads();

    int ct = tid & 31, rt = tid >> 5;
    int c0 = ct * 4, r0 = rt * 8;
    u64 acc[4][4];
#pragma unroll
    for (int rp = 0; rp < 4; rp++)
#pragma unroll
        for (int c = 0; c < 4; c++) acc[rp][c] = 0ull;

#pragma unroll 2
    for (int k = 0; k < DD; k++) {
        float4 w1 = __ldg(reinterpret_cast<const float4*>(&Wt[k * 256 + c0]));
        float4 w2 = __ldg(reinterpret_cast<const float4*>(&Wt[k * 256 + 128 + c0]));
        float4 xa = *reinterpret_cast<const float4*>(&xt[k * XTS + r0]);
        float4 xb = *reinterpret_cast<const float4*>(&xt[k * XTS + r0 + 4]);
        float4 aa = *reinterpret_cast<const float4*>(&at[k * XTS + r0]);
        float4 ab = *reinterpret_cast<const float4*>(&at[k * XTS + r0 + 4]);
        u64 xp[4] = {pk2(xa.x, xa.y), pk2(xa.z, xa.w), pk2(xb.x, xb.y), pk2(xb.z, xb.w)};
        u64 ap[4] = {pk2(aa.x, aa.y), pk2(aa.z, aa.w), pk2(ab.x, ab.y), pk2(ab.z, ab.w)};
        u64 w1d[4] = {dp2(w1.x), dp2(w1.y), dp2(w1.z), dp2(w1.w)};
        u64 w2d[4] = {dp2(w2.x), dp2(w2.y), dp2(w2.z), dp2(w2.w)};
#pragma unroll
        for (int rp = 0; rp < 4; rp++)
#pragma unroll
            for (int c = 0; c < 4; c++) {
                fma2(acc[rp][c], xp[rp], w1d[c]);
                fma2(acc[rp][c], ap[rp], w2d[c]);
            }
    }
    float4 bb = *reinterpret_cast<const float4*>(&b[c0]);
    __syncthreads();
    float* hs = xt;

#pragma unroll
    for (int rp = 0; rp < 4; rp++) {
        float lo[4], hi[4];
#pragma unroll
        for (int c = 0; c < 4; c++) up2(acc[rp][c], lo[c], hi[c]);
        int rla = r0 + 2 * rp;
        int ra = row0 + rla;
        float4 xra = make_float4(0.f, 0.f, 0.f, 0.f);
        float4 xrb = make_float4(0.f, 0.f, 0.f, 0.f);
        if (ra < N)     xra = *reinterpret_cast<const float4*>(&X[(size_t)ra * DD + c0]);
        if (ra + 1 < N) xrb = *reinterpret_cast<const float4*>(&X[(size_t)(ra + 1) * DD + c0]);
        float4 oa, ob;
        oa.x = fmaxf(lo[0] + bb.x, 0.f) + xra.x;
        oa.y = fmaxf(lo[1] + bb.y, 0.f) + xra.y;
        oa.z = fmaxf(lo[2] + bb.z, 0.f) + xra.z;
        oa.w = fmaxf(lo[3] + bb.w, 0.f) + xra.w;
        ob.x = fmaxf(hi[0] + bb.x, 0.f) + xrb.x;
        ob.y = fmaxf(hi[1] + bb.y, 0.f) + xrb.y;
        ob.z = fmaxf(hi[2] + bb.z, 0.f) + xrb.z;
        ob.w = fmaxf(hi[3] + bb.w, 0.f) + xrb.w;
        *reinterpret_cast<float4*>(&hs[rla * DD + c0]) = oa;
        *reinterpret_cast<float4*>(&hs[(rla + 1) * DD + c0]) = ob;
    }
    __syncthreads();

    int lane = tid & 31;
    float4 gg  = *reinterpret_cast<const float4*>(&g[lane * 4]);
    float4 bev = *reinterpret_cast<const float4*>(&be[lane * 4]);
    for (int r = 0; r < 8; r++) {
        int rl = rt * 8 + r;
        int row = row0 + rl;
        float4 v = *reinterpret_cast<const float4*>(&hs[rl * DD + lane * 4]);
        float s  = v.x + v.y + v.z + v.w;
        float s2 = v.x * v.x + v.y * v.y + v.z * v.z + v.w * v.w;
#pragma unroll
        for (int o_ = 16; o_; o_ >>= 1) {
            s  += __shfl_xor_sync(0xFFFFFFFFu, s, o_);
            s2 += __shfl_xor_sync(0xFFFFFFFFu, s2, o_);
        }
        float mu  = s * (1.0f / 128.0f);
        float var = s2 * (1.0f / 128.0f) - mu * mu;
        float rstd = rsqrtf(var + 1e-5f);
        if (row < N) {
            float4 o;
            o.x = (v.x - mu) * rstd * gg.x + bev.x;
            o.y = (v.y - mu) * rstd * gg.y + bev.y;
            o.z = (v.z - mu) * rstd * gg.z + bev.z;
            o.w = (v.w - mu) * rstd * gg.w + bev.w;
            *reinterpret_cast<float4*>(&out[(size_t)row * DD + lane * 4]) = o;
        }
    }
}

// ---------------- launch ----------------
extern "C" void kernel_launch(void* const* d_in, const int* in_sizes, int n_in,
                              void* d_out, int out_size)
{
    const float* x_drug  = (const float*)d_in[0];
    const float* x_prot  = (const float*)d_in[1];
    const float* Wagg_dd = (const float*)d_in[2];
    const float* Wagg_dp = (const float*)d_in[3];
    const float* Wagg_pd = (const float*)d_in[4];
    const float* W_drug  = (const float*)d_in[5];
    const float* b_drug  = (const float*)d_in[6];
    const float* W_prot  = (const float*)d_in[7];
    const float* b_prot  = (const float*)d_in[8];
    const float* g_drug  = (const float*)d_in[9];
    const float* be_drug = (const float*)d_in[10];
    const float* g_prot  = (const float*)d_in[11];
    const float* be_prot = (const float*)d_in[12];
    const int* dd_src = (const int*)d_in[13];
    const int* dd_dst = (const int*)d_in[14];
    const int* dp_src = (const int*)d_in[15];
    const int* dp_dst = (const int*)d_in[16];
    const int* pd_src = (const int*)d_in[17];
    const int* pd_dst = (const int*)d_in[18];
    float* out = (float*)d_out;

    float *Hdd, *Hdp, *Hpd, *Adrug, *Aprot;
    float *WtDD, *WtDP, *WtPD, *WtDR, *WtPR;
    int *off_dd, *off_pd, *off_dp, *esrc_dd, *esrc_pd, *esrc_dp;
    cudaGetSymbolAddress((void**)&Hdd, g_Hdd);
    cudaGetSymbolAddress((void**)&Hdp, g_Hdp);
    cudaGetSymbolAddress((void**)&Hpd, g_Hpd);
    cudaGetSymbolAddress((void**)&Adrug, g_Adrug);
    cudaGetSymbolAddress((void**)&Aprot, g_Aprot);
    cudaGetSymbolAddress((void**)&WtDD, g_WtDD);
    cudaGetSymbolAddress((void**)&WtDP, g_WtDP);
    cudaGetSymbolAddress((void**)&WtPD, g_WtPD);
    cudaGetSymbolAddress((void**)&WtDR, g_WtDR);
    cudaGetSymbolAddress((void**)&WtPR, g_WtPR);
    cudaGetSymbolAddress((void**)&off_dd, g_off_dd);
    cudaGetSymbolAddress((void**)&off_pd, g_off_pd);
    cudaGetSymbolAddress((void**)&off_dp, g_off_dp);
    cudaGetSymbolAddress((void**)&esrc_dd, g_esrc_dd);
    cudaGetSymbolAddress((void**)&esrc_pd, g_esrc_pd);
    cudaGetSymbolAddress((void**)&esrc_dp, g_esrc_dp);

    // CSR build + weight prep (parallel scan)
    init_all<<<256, 256>>>(Wagg_dd, Wagg_dp, Wagg_pd, W_drug, W_prot);
    count_all<<<(EDD + EPD + EDP + 255) / 256, 256>>>(dd_dst, pd_dst, dp_dst);
    chunk_sums<<<NCH_TOT, 1024>>>();
    scan_partials<<<1, 64>>>();
    chunk_scan<<<NCH_TOT, 1024>>>();
    fill_all<<<(EDD + EPD + EDP + 255) / 256, 256>>>(dd_src, dd_dst, pd_src, pd_dst, dp_src, dp_dst);

    // GEMMs + gathers, interleaved for L2 residency
    agg_gemm_relu<<<(NDRUG + 63) / 64, 256>>>(x_drug, WtDD, Hdd, NDRUG);
    edge_gather<<<(NDRUG * 32 + 255) / 256, 256>>>(Hdd, esrc_dd, off_dd, Adrug, NDRUG, 0);

    agg_gemm_relu<<<(NPROT + 63) / 64, 256>>>(x_prot, WtPD, Hpd, NPROT);
    edge_gather<<<(NDRUG * 32 + 255) / 256, 256>>>(Hpd, esrc_pd, off_pd, Adrug, NDRUG, 1);

    agg_gemm_relu<<<(NDRUG + 63) / 64, 256>>>(x_drug, WtDP, Hdp, NDRUG);
    edge_gather<<<(NPROT * 32 + 255) / 256, 256>>>(Hdp, esrc_dp, off_dp, Aprot, NPROT, 0);

    node_update<<<(NDRUG + 63) / 64, 256>>>(
        x_drug, Adrug, WtDR, b_drug, g_drug, be_drug, out, NDRUG);
    node_update<<<(NPROT + 63) / 64, 256>>>(
        x_prot, Aprot, WtPR, b_prot, g_prot, be_prot,
        out + (size_t)NDRUG * DD, NPROT);
}

// round 10
// speedup vs baseline: 1.5367x; 1.1035x over previous
#include <cuda_runtime.h>
#include <cstdint>

#define NDRUG 100000
#define NPROT 50000
#define EDD 800000
#define EDP 600000
#define EPD 600000
#define DD 128
#define XTS 68

// chunked scan geometry
#define CH 4096
#define NCH_DD 25
#define NCH_PD 25
#define NCH_DP 13
#define NCH_TOT (NCH_DD + NCH_PD + NCH_DP)   // 63

typedef unsigned long long u64;

__device__ __forceinline__ u64 pk2(float lo, float hi) {
    u64 r; asm("mov.b64 %0,{%1,%2};" : "=l"(r) : "f"(lo), "f"(hi)); return r;
}
__device__ __forceinline__ u64 dp2(float v) {
    u64 r; asm("mov.b64 %0,{%1,%1};" : "=l"(r) : "f"(v)); return r;
}
__device__ __forceinline__ void fma2(u64& d, u64 a, u64 b) {
    asm("fma.rn.f32x2 %0,%1,%2,%3;" : "=l"(d) : "l"(a), "l"(b), "l"(d));
}
__device__ __forceinline__ void up2(u64 v, float& lo, float& hi) {
    asm("mov.b64 {%0,%1},%2;" : "=f"(lo), "=f"(hi) : "l"(v));
}

// ---------------- scratch ----------------
__device__ __align__(16) float g_Hdd[(size_t)NDRUG * DD];
__device__ __align__(16) float g_Hdp[(size_t)NDRUG * DD];
__device__ __align__(16) float g_Hpd[(size_t)NPROT * DD];
__device__ __align__(16) float g_Adrug[(size_t)NDRUG * DD];
__device__ __align__(16) float g_Aprot[(size_t)NPROT * DD];
// CSR
__device__ __align__(16) int g_cnt_dd[NDRUG];
__device__ __align__(16) int g_cnt_pd[NDRUG];
__device__ __align__(16) int g_cnt_dp[NPROT];
__device__ __align__(16) int g_off_dd[NDRUG + 4];
__device__ __align__(16) int g_off_pd[NDRUG + 4];
__device__ __align__(16) int g_off_dp[NPROT + 4];
__device__ __align__(16) int g_cur_dd[NDRUG + 4];
__device__ __align__(16) int g_cur_pd[NDRUG + 4];
__device__ __align__(16) int g_cur_dp[NPROT + 4];
__device__ int g_esrc_dd[EDD];
__device__ int g_esrc_pd[EPD];
__device__ int g_esrc_dp[EDP];
__device__ int g_part[NCH_TOT];
__device__ int g_pbase[NCH_TOT];
// transposed weights
__device__ __align__(16) float g_WtDD[DD * DD];
__device__ __align__(16) float g_WtDP[DD * DD];
__device__ __align__(16) float g_WtPD[DD * DD];
__device__ __align__(16) float g_WtDR[DD * 2 * DD];
__device__ __align__(16) float g_WtPR[DD * 2 * DD];

// ---------------- host-side stream/event resources (static init; no device mem) ----------------
struct GpuRes {
    cudaStream_t s1;
    cudaEvent_t eFork, eDD, ePD, eDP, eGPD, eEnd;
    GpuRes() {
        cudaStreamCreateWithFlags(&s1, cudaStreamNonBlocking);
        cudaEventCreateWithFlags(&eFork, cudaEventDisableTiming);
        cudaEventCreateWithFlags(&eDD,   cudaEventDisableTiming);
        cudaEventCreateWithFlags(&ePD,   cudaEventDisableTiming);
        cudaEventCreateWithFlags(&eDP,   cudaEventDisableTiming);
        cudaEventCreateWithFlags(&eGPD,  cudaEventDisableTiming);
        cudaEventCreateWithFlags(&eEnd,  cudaEventDisableTiming);
    }
};
static GpuRes g_res;

// ---------------- weight transpose (s0 branch) ----------------
__global__ void prep_weights(const float* __restrict__ Wdd, const float* __restrict__ Wdp,
                             const float* __restrict__ Wpd, const float* __restrict__ Wdr,
                             const float* __restrict__ Wpr)
{
    int t = blockIdx.x * blockDim.x + threadIdx.x;
    int stride = gridDim.x * blockDim.x;
    for (int i = t; i < DD * DD; i += stride) {
        int c = i >> 7, k = i & 127;
        g_WtDD[k * DD + c] = Wdd[i];
        g_WtDP[k * DD + c] = Wdp[i];
        g_WtPD[k * DD + c] = Wpd[i];
    }
    for (int i = t; i < DD * 2 * DD; i += stride) {
        int c = i >> 8, col = i & 255;
        int k = col & 127, half = col >> 7;
        g_WtDR[k * 256 + half * 128 + c] = Wdr[i];
        g_WtPR[k * 256 + half * 128 + c] = Wpr[i];
    }
}

// ---------------- CSR build (s1 branch) ----------------
__global__ void zero_counts() {
    int t = blockIdx.x * blockDim.x + threadIdx.x;
    int stride = gridDim.x * blockDim.x;
    for (int i = t; i < NDRUG; i += stride) { g_cnt_dd[i] = 0; g_cnt_pd[i] = 0; }
    for (int i = t; i < NPROT; i += stride) g_cnt_dp[i] = 0;
}

__global__ void count_all(const int* __restrict__ dd, const int* __restrict__ pd,
                          const int* __restrict__ dp) {
    int t = blockIdx.x * blockDim.x + threadIdx.x;
    if (t < EDD) atomicAdd(&g_cnt_dd[__ldg(&dd[t])], 1);
    else if (t < EDD + EPD) atomicAdd(&g_cnt_pd[__ldg(&pd[t - EDD])], 1);
    else if (t < EDD + EPD + EDP) atomicAdd(&g_cnt_dp[__ldg(&dp[t - EDD - EPD])], 1);
}

__device__ __forceinline__ void chunk_map(int b, const int*& cnt, int*& offs, int*& cur,
                                          int& base, int& n) {
    if (b < NCH_DD)              { cnt = g_cnt_dd; offs = g_off_dd; cur = g_cur_dd; base = b * CH; n = NDRUG; }
    else if (b < NCH_DD + NCH_PD){ cnt = g_cnt_pd; offs = g_off_pd; cur = g_cur_pd; base = (b - NCH_DD) * CH; n = NDRUG; }
    else                         { cnt = g_cnt_dp; offs = g_off_dp; cur = g_cur_dp; base = (b - NCH_DD - NCH_PD) * CH; n = NPROT; }
}

__global__ __launch_bounds__(1024) void chunk_sums() {
    const int* cnt; int* offs; int* cur; int base, n;
    chunk_map(blockIdx.x, cnt, offs, cur, base, n);
    int i0 = base + threadIdx.x * 4;
    int4 c = make_int4(0, 0, 0, 0);
    if (i0 < n) c = *reinterpret_cast<const int4*>(&cnt[i0]);
    int tot = c.x + c.y + c.z + c.w;
    __shared__ int ws[32];
    int lane = threadIdx.x & 31, wid = threadIdx.x >> 5;
#pragma unroll
    for (int o = 16; o; o >>= 1) tot += __shfl_xor_sync(0xFFFFFFFFu, tot, o);
    if (lane == 0) ws[wid] = tot;
    __syncthreads();
    if (wid == 0) {
        int v = ws[lane];
#pragma unroll
        for (int o = 16; o; o >>= 1) v += __shfl_xor_sync(0xFFFFFFFFu, v, o);
        if (lane == 0) g_part[blockIdx.x] = v;
    }
}

__global__ void scan_partials() {
    __shared__ int s[64];
    int t = threadIdx.x;
    int v = (t < NCH_TOT) ? g_part[t] : 0;
    s[t] = v;
    __syncthreads();
#pragma unroll
    for (int o = 1; o < 64; o <<= 1) {
        int add = (t >= o) ? s[t - o] : 0;
        __syncthreads();
        s[t] += add;
        __syncthreads();
    }
    if (t < NCH_TOT) {
        int excl = s[t] - v;
        int segoff = (t >= NCH_DD + NCH_PD) ? (EDD + EPD) : (t >= NCH_DD ? EDD : 0);
        g_pbase[t] = excl - segoff;
    }
    if (t == 0) {
        g_off_dd[NDRUG] = EDD;
        g_off_pd[NDRUG] = EPD;
        g_off_dp[NPROT] = EDP;
    }
}

__global__ __launch_bounds__(1024) void chunk_scan() {
    const int* cnt; int* offs; int* cur; int base, n;
    chunk_map(blockIdx.x, cnt, offs, cur, base, n);
    int carry = g_pbase[blockIdx.x];
    __shared__ int wsum[32];
    int tid = threadIdx.x, lane = tid & 31, wid = tid >> 5;
    int i0 = base + tid * 4;
    int4 c = make_int4(0, 0, 0, 0);
    if (i0 < n) c = *reinterpret_cast<const int4*>(&cnt[i0]);
    int tot = c.x + c.y + c.z + c.w;
    int incl = tot;
#pragma unroll
    for (int o = 1; o < 32; o <<= 1) {
        int v = __shfl_up_sync(0xFFFFFFFFu, incl, o);
        if (lane >= o) incl += v;
    }
    if (lane == 31) wsum[wid] = incl;
    __syncthreads();
    if (wid == 0) {
        int v = wsum[lane];
        int wincl = v;
#pragma unroll
        for (int o = 1; o < 32; o <<= 1) {
            int t2 = __shfl_up_sync(0xFFFFFFFFu, wincl, o);
            if (lane >= o) wincl += t2;
        }
        wsum[lane] = wincl - v;
    }
    __syncthreads();
    int excl = carry + wsum[wid] + incl - tot;
    if (i0 < n) {
        int e0 = excl, e1 = e0 + c.x, e2 = e1 + c.y, e3 = e2 + c.z;
        *reinterpret_cast<int4*>(&offs[i0]) = make_int4(e0, e1, e2, e3);
        *reinterpret_cast<int4*>(&cur[i0])  = make_int4(e0, e1, e2, e3);
    }
}

__global__ void fill_all(const int* __restrict__ dd_s, const int* __restrict__ dd_d,
                         const int* __restrict__ pd_s, const int* __restrict__ pd_d,
                         const int* __restrict__ dp_s, const int* __restrict__ dp_d) {
    int t = blockIdx.x * blockDim.x + threadIdx.x;
    if (t < EDD) {
        int slot = atomicAdd(&g_cur_dd[__ldg(&dd_d[t])], 1);
        g_esrc_dd[slot] = __ldg(&dd_s[t]);
    } else if (t < EDD + EPD) {
        int e = t - EDD;
        int slot = atomicAdd(&g_cur_pd[__ldg(&pd_d[e])], 1);
        g_esrc_pd[slot] = __ldg(&pd_s[e]);
    } else if (t < EDD + EPD + EDP) {
        int e = t - EDD - EPD;
        int slot = atomicAdd(&g_cur_dp[__ldg(&dp_d[e])], 1);
        g_esrc_dp[slot] = __ldg(&dp_s[e]);
    }
}

// ---------------- GEMM + ReLU (proven R4/R8 version) ----------------
__global__ __launch_bounds__(256, 3) void agg_gemm_relu(
    const float* __restrict__ X, const float* __restrict__ Wt,
    float* __restrict__ H, int N)
{
    __shared__ float xt[DD * XTS];

    int tid = threadIdx.x;
    int row0 = blockIdx.x * 64;
    for (int j = tid; j < 64 * 32; j += 256) {
        int r = j & 63, qg = j >> 6;
        int row = row0 + r;
        float4 v = make_float4(0.f, 0.f, 0.f, 0.f);
        if (row < N) v = *reinterpret_cast<const float4*>(&X[(size_t)row * DD + qg * 4]);
        xt[(qg * 4 + 0) * XTS + r] = v.x;
        xt[(qg * 4 + 1) * XTS + r] = v.y;
        xt[(qg * 4 + 2) * XTS + r] = v.z;
        xt[(qg * 4 + 3) * XTS + r] = v.w;
    }
    __syncthreads();

    int ct = tid & 31, rt = tid >> 5;
    int c0 = ct * 4, r0 = rt * 8;
    u64 acc[4][4];
#pragma unroll
    for (int rp = 0; rp < 4; rp++)
#pragma unroll
        for (int c = 0; c < 4; c++) acc[rp][c] = 0ull;

#pragma unroll 4
    for (int k = 0; k < DD; k++) {
        float4 w = __ldg(reinterpret_cast<const float4*>(&Wt[k * DD + c0]));
        float4 xa = *reinterpret_cast<const float4*>(&xt[k * XTS + r0]);
        float4 xb = *reinterpret_cast<const float4*>(&xt[k * XTS + r0 + 4]);
        u64 xp[4] = {pk2(xa.x, xa.y), pk2(xa.z, xa.w), pk2(xb.x, xb.y), pk2(xb.z, xb.w)};
        u64 wd[4] = {dp2(w.x), dp2(w.y), dp2(w.z), dp2(w.w)};
#pragma unroll
        for (int rp = 0; rp < 4; rp++)
#pragma unroll
            for (int c = 0; c < 4; c++) fma2(acc[rp][c], xp[rp], wd[c]);
    }

#pragma unroll
    for (int rp = 0; rp < 4; rp++) {
        float lo[4], hi[4];
#pragma unroll
        for (int c = 0; c < 4; c++) up2(acc[rp][c], lo[c], hi[c]);
        int ra = row0 + r0 + 2 * rp;
        if (ra < N) {
            float4 o = make_float4(fmaxf(lo[0], 0.f), fmaxf(lo[1], 0.f),
                                   fmaxf(lo[2], 0.f), fmaxf(lo[3], 0.f));
            *reinterpret_cast<float4*>(&H[(size_t)ra * DD + c0]) = o;
        }
        if (ra + 1 < N) {
            float4 o = make_float4(fmaxf(hi[0], 0.f), fmaxf(hi[1], 0.f),
                                   fmaxf(hi[2], 0.f), fmaxf(hi[3], 0.f));
            *reinterpret_cast<float4*>(&H[(size_t)(ra + 1) * DD + c0]) = o;
        }
    }
}

// ---------------- CSR gather (proven version) ----------------
__global__ __launch_bounds__(256) void edge_gather(
    const float* __restrict__ H, const int* __restrict__ esrc,
    const int* __restrict__ offs, float* __restrict__ A, int N, int mode)
{
    int w = (blockIdx.x * blockDim.x + threadIdx.x) >> 5;
    if (w >= N) return;
    int lane = threadIdx.x & 31;
    int beg = __ldg(&offs[w]), end = __ldg(&offs[w + 1]);
    float4 acc = make_float4(0.f, 0.f, 0.f, 0.f);
    int e = beg;
    for (; e + 4 <= end; e += 4) {
        int s0 = __ldg(&esrc[e]);
        int s1 = __ldg(&esrc[e + 1]);
        int s2 = __ldg(&esrc[e + 2]);
        int s3 = __ldg(&esrc[e + 3]);
        float4 v0 = __ldg(reinterpret_cast<const float4*>(&H[(size_t)s0 * DD + lane * 4]));
        float4 v1 = __ldg(reinterpret_cast<const float4*>(&H[(size_t)s1 * DD + lane * 4]));
        float4 v2 = __ldg(reinterpret_cast<const float4*>(&H[(size_t)s2 * DD + lane * 4]));
        float4 v3 = __ldg(reinterpret_cast<const float4*>(&H[(size_t)s3 * DD + lane * 4]));
        acc.x += (v0.x + v1.x) + (v2.x + v3.x);
        acc.y += (v0.y + v1.y) + (v2.y + v3.y);
        acc.z += (v0.z + v1.z) + (v2.z + v3.z);
        acc.w += (v0.w + v1.w) + (v2.w + v3.w);
    }
    for (; e < end; e++) {
        int s = __ldg(&esrc[e]);
        float4 v = __ldg(reinterpret_cast<const float4*>(&H[(size_t)s * DD + lane * 4]));
        acc.x += v.x; acc.y += v.y; acc.z += v.z; acc.w += v.w;
    }
    float inv = 1.0f / fmaxf((float)(end - beg), 1.0f);
    float4 o = make_float4(acc.x * inv, acc.y * inv, acc.z * inv, acc.w * inv);
    float* p = &A[(size_t)w * DD + lane * 4];
    if (mode) {
        float4 prev = *reinterpret_cast<const float4*>(p);
        o.x = 0.5f * (prev.x + o.x);
        o.y = 0.5f * (prev.y + o.y);
        o.z = 0.5f * (prev.z + o.z);
        o.w = 0.5f * (prev.w + o.w);
    }
    *reinterpret_cast<float4*>(p) = o;
}

// ---------------- fused node update (proven version) ----------------
__global__ __launch_bounds__(256, 2) void node_update(
    const float* __restrict__ X,
    const float* __restrict__ A,
    const float* __restrict__ Wt,
    const float* __restrict__ b,
    const float* __restrict__ g,
    const float* __restrict__ be,
    float* __restrict__ out, int N)
{
    __shared__ float xt[DD * XTS];
    __shared__ float at[DD * XTS];

    int tid = threadIdx.x;
    int row0 = blockIdx.x * 64;
    for (int j = tid; j < 64 * 32; j += 256) {
        int r = j & 63, qg = j >> 6;
        int row = row0 + r;
        float4 xv = make_float4(0.f, 0.f, 0.f, 0.f);
        float4 av = make_float4(0.f, 0.f, 0.f, 0.f);
        if (row < N) {
            xv = *reinterpret_cast<const float4*>(&X[(size_t)row * DD + qg * 4]);
            av = *reinterpret_cast<const float4*>(&A[(size_t)row * DD + qg * 4]);
        }
        xt[(qg * 4 + 0) * XTS + r] = xv.x;
        xt[(qg * 4 + 1) * XTS + r] = xv.y;
        xt[(qg * 4 + 2) * XTS + r] = xv.z;
        xt[(qg * 4 + 3) * XTS + r] = xv.w;
        at[(qg * 4 + 0) * XTS + r] = av.x;
        at[(qg * 4 + 1) * XTS + r] = av.y;
        at[(qg * 4 + 2) * XTS + r] = av.z;
        at[(qg * 4 + 3) * XTS + r] = av.w;
    }
    __syncthreads();

    int ct = tid & 31, rt = tid >> 5;
    int c0 = ct * 4, r0 = rt * 8;
    u64 acc[4][4];
#pragma unroll
    for (int rp = 0; rp < 4; rp++)
#pragma unroll
        for (int c = 0; c < 4; c++) acc[rp][c] = 0ull;

#pragma unroll 2
    for (int k = 0; k < DD; k++) {
        float4 w1 = __ldg(reinterpret_cast<const float4*>(&Wt[k * 256 + c0]));
        float4 w2 = __ldg(reinterpret_cast<const float4*>(&Wt[k * 256 + 128 + c0]));
        float4 xa = *reinterpret_cast<const float4*>(&xt[k * XTS + r0]);
        float4 xb = *reinterpret_cast<const float4*>(&xt[k * XTS + r0 + 4]);
        float4 aa = *reinterpret_cast<const float4*>(&at[k * XTS + r0]);
        float4 ab = *reinterpret_cast<const float4*>(&at[k * XTS + r0 + 4]);
        u64 xp[4] = {pk2(xa.x, xa.y), pk2(xa.z, xa.w), pk2(xb.x, xb.y), pk2(xb.z, xb.w)};
        u64 ap[4] = {pk2(aa.x, aa.y), pk2(aa.z, aa.w), pk2(ab.x, ab.y), pk2(ab.z, ab.w)};
        u64 w1d[4] = {dp2(w1.x), dp2(w1.y), dp2(w1.z), dp2(w1.w)};
        u64 w2d[4] = {dp2(w2.x), dp2(w2.y), dp2(w2.z), dp2(w2.w)};
#pragma unroll
        for (int rp = 0; rp < 4; rp++)
#pragma unroll
            for (int c = 0; c < 4; c++) {
                fma2(acc[rp][c], xp[rp], w1d[c]);
                fma2(acc[rp][c], ap[rp], w2d[c]);
            }
    }
    float4 bb = *reinterpret_cast<const float4*>(&b[c0]);
    __syncthreads();
    float* hs = xt;

#pragma unroll
    for (int rp = 0; rp < 4; rp++) {
        float lo[4], hi[4];
#pragma unroll
        for (int c = 0; c < 4; c++) up2(acc[rp][c], lo[c], hi[c]);
        int rla = r0 + 2 * rp;
        int ra = row0 + rla;
        float4 xra = make_float4(0.f, 0.f, 0.f, 0.f);
        float4 xrb = make_float4(0.f, 0.f, 0.f, 0.f);
        if (ra < N)     xra = *reinterpret_cast<const float4*>(&X[(size_t)ra * DD + c0]);
        if (ra + 1 < N) xrb = *reinterpret_cast<const float4*>(&X[(size_t)(ra + 1) * DD + c0]);
        float4 oa, ob;
        oa.x = fmaxf(lo[0] + bb.x, 0.f) + xra.x;
        oa.y = fmaxf(lo[1] + bb.y, 0.f) + xra.y;
        oa.z = fmaxf(lo[2] + bb.z, 0.f) + xra.z;
        oa.w = fmaxf(lo[3] + bb.w, 0.f) + xra.w;
        ob.x = fmaxf(hi[0] + bb.x, 0.f) + xrb.x;
        ob.y = fmaxf(hi[1] + bb.y, 0.f) + xrb.y;
        ob.z = fmaxf(hi[2] + bb.z, 0.f) + xrb.z;
        ob.w = fmaxf(hi[3] + bb.w, 0.f) + xrb.w;
        *reinterpret_cast<float4*>(&hs[rla * DD + c0]) = oa;
        *reinterpret_cast<float4*>(&hs[(rla + 1) * DD + c0]) = ob;
    }
    __syncthreads();

    int lane = tid & 31;
    float4 gg  = *reinterpret_cast<const float4*>(&g[lane * 4]);
    float4 bev = *reinterpret_cast<const float4*>(&be[lane * 4]);
    for (int r = 0; r < 8; r++) {
        int rl = rt * 8 + r;
        int row = row0 + rl;
        float4 v = *reinterpret_cast<const float4*>(&hs[rl * DD + lane * 4]);
        float s  = v.x + v.y + v.z + v.w;
        float s2 = v.x * v.x + v.y * v.y + v.z * v.z + v.w * v.w;
#pragma unroll
        for (int o_ = 16; o_; o_ >>= 1) {
            s  += __shfl_xor_sync(0xFFFFFFFFu, s, o_);
            s2 += __shfl_xor_sync(0xFFFFFFFFu, s2, o_);
        }
        float mu  = s * (1.0f / 128.0f);
        float var = s2 * (1.0f / 128.0f) - mu * mu;
        float rstd = rsqrtf(var + 1e-5f);
        if (row < N) {
            float4 o;
            o.x = (v.x - mu) * rstd * gg.x + bev.x;
            o.y = (v.y - mu) * rstd * gg.y + bev.y;
            o.z = (v.z - mu) * rstd * gg.z + bev.z;
            o.w = (v.w - mu) * rstd * gg.w + bev.w;
            *reinterpret_cast<float4*>(&out[(size_t)row * DD + lane * 4]) = o;
        }
    }
}

// ---------------- launch: two-branch DAG via fork/join events ----------------
extern "C" void kernel_launch(void* const* d_in, const int* in_sizes, int n_in,
                              void* d_out, int out_size)
{
    const float* x_drug  = (const float*)d_in[0];
    const float* x_prot  = (const float*)d_in[1];
    const float* Wagg_dd = (const float*)d_in[2];
    const float* Wagg_dp = (const float*)d_in[3];
    const float* Wagg_pd = (const float*)d_in[4];
    const float* W_drug  = (const float*)d_in[5];
    const float* b_drug  = (const float*)d_in[6];
    const float* W_prot  = (const float*)d_in[7];
    const float* b_prot  = (const float*)d_in[8];
    const float* g_drug  = (const float*)d_in[9];
    const float* be_drug = (const float*)d_in[10];
    const float* g_prot  = (const float*)d_in[11];
    const float* be_prot = (const float*)d_in[12];
    const int* dd_src = (const int*)d_in[13];
    const int* dd_dst = (const int*)d_in[14];
    const int* dp_src = (const int*)d_in[15];
    const int* dp_dst = (const int*)d_in[16];
    const int* pd_src = (const int*)d_in[17];
    const int* pd_dst = (const int*)d_in[18];
    float* out = (float*)d_out;

    float *Hdd, *Hdp, *Hpd, *Adrug, *Aprot;
    float *WtDD, *WtDP, *WtPD, *WtDR, *WtPR;
    int *off_dd, *off_pd, *off_dp, *esrc_dd, *esrc_pd, *esrc_dp;
    cudaGetSymbolAddress((void**)&Hdd, g_Hdd);
    cudaGetSymbolAddress((void**)&Hdp, g_Hdp);
    cudaGetSymbolAddress((void**)&Hpd, g_Hpd);
    cudaGetSymbolAddress((void**)&Adrug, g_Adrug);
    cudaGetSymbolAddress((void**)&Aprot, g_Aprot);
    cudaGetSymbolAddress((void**)&WtDD, g_WtDD);
    cudaGetSymbolAddress((void**)&WtDP, g_WtDP);
    cudaGetSymbolAddress((void**)&WtPD, g_WtPD);
    cudaGetSymbolAddress((void**)&WtDR, g_WtDR);
    cudaGetSymbolAddress((void**)&WtPR, g_WtPR);
    cudaGetSymbolAddress((void**)&off_dd, g_off_dd);
    cudaGetSymbolAddress((void**)&off_pd, g_off_pd);
    cudaGetSymbolAddress((void**)&off_dp, g_off_dp);
    cudaGetSymbolAddress((void**)&esrc_dd, g_esrc_dd);
    cudaGetSymbolAddress((void**)&esrc_pd, g_esrc_pd);
    cudaGetSymbolAddress((void**)&esrc_dp, g_esrc_dp);

    cudaStream_t s1 = g_res.s1;

    // ---- fork s1 off the main (captured) stream ----
    cudaEventRecord(g_res.eFork, 0);
    cudaStreamWaitEvent(s1, g_res.eFork, 0);

    // ---- s1: CSR build chain ----
    zero_counts<<<256, 256, 0, s1>>>();
    count_all<<<(EDD + EPD + EDP + 255) / 256, 256, 0, s1>>>(dd_dst, pd_dst, dp_dst);
    chunk_sums<<<NCH_TOT, 1024, 0, s1>>>();
    scan_partials<<<1, 64, 0, s1>>>();
    chunk_scan<<<NCH_TOT, 1024, 0, s1>>>();
    fill_all<<<(EDD + EPD + EDP + 255) / 256, 256, 0, s1>>>(dd_src, dd_dst, pd_src, pd_dst, dp_src, dp_dst);

    // ---- s0: weight prep + GEMMs ----
    prep_weights<<<256, 256>>>(Wagg_dd, Wagg_dp, Wagg_pd, W_drug, W_prot);
    agg_gemm_relu<<<(NDRUG + 63) / 64, 256>>>(x_drug, WtDD, Hdd, NDRUG);
    cudaEventRecord(g_res.eDD, 0);
    agg_gemm_relu<<<(NPROT + 63) / 64, 256>>>(x_prot, WtPD, Hpd, NPROT);
    cudaEventRecord(g_res.ePD, 0);
    agg_gemm_relu<<<(NDRUG + 63) / 64, 256>>>(x_drug, WtDP, Hdp, NDRUG);
    cudaEventRecord(g_res.eDP, 0);

    // ---- s1: gathers (each waits on its GEMM; CSR already ordered on s1) ----
    cudaStreamWaitEvent(s1, g_res.eDD, 0);
    edge_gather<<<(NDRUG * 32 + 255) / 256, 256, 0, s1>>>(Hdd, esrc_dd, off_dd, Adrug, NDRUG, 0);
    cudaStreamWaitEvent(s1, g_res.ePD, 0);
    edge_gather<<<(NDRUG * 32 + 255) / 256, 256, 0, s1>>>(Hpd, esrc_pd, off_pd, Adrug, NDRUG, 1);
    cudaEventRecord(g_res.eGPD, s1);
    cudaStreamWaitEvent(s1, g_res.eDP, 0);
    edge_gather<<<(NPROT * 32 + 255) / 256, 256, 0, s1>>>(Hdp, esrc_dp, off_dp, Aprot, NPROT, 0);
    node_update<<<(NPROT + 63) / 64, 256, 0, s1>>>(
        x_prot, Aprot, WtPR, b_prot, g_prot, be_prot,
        out + (size_t)NDRUG * DD, NPROT);
    cudaEventRecord(g_res.eEnd, s1);

    // ---- s0: drug node update (needs Adrug = gathers dd+pd), then join ----
    cudaStreamWaitEvent(0, g_res.eGPD, 0);
    node_update<<<(NDRUG + 63) / 64, 256>>>(
        x_drug, Adrug, WtDR, b_drug, g_drug, be_drug, out, NDRUG);
    cudaStreamWaitEvent(0, g_res.eEnd, 0);
}

// round 11
// speedup vs baseline: 1.5538x; 1.0111x over previous
#include <cuda_runtime.h>
#include <cstdint>

#define NDRUG 100000
#define NPROT 50000
#define EDD 800000
#define EDP 600000
#define EPD 600000
#define DD 128
#define XTS 68

// chunked scan geometry
#define CH 4096
#define NCH_DD 25
#define NCH_PD 25
#define NCH_DP 13
#define NCH_TOT (NCH_DD + NCH_PD + NCH_DP)   // 63

typedef unsigned long long u64;

__device__ __forceinline__ u64 pk2(float lo, float hi) {
    u64 r; asm("mov.b64 %0,{%1,%2};" : "=l"(r) : "f"(lo), "f"(hi)); return r;
}
__device__ __forceinline__ u64 dp2(float v) {
    u64 r; asm("mov.b64 %0,{%1,%1};" : "=l"(r) : "f"(v)); return r;
}
__device__ __forceinline__ void fma2(u64& d, u64 a, u64 b) {
    asm("fma.rn.f32x2 %0,%1,%2,%3;" : "=l"(d) : "l"(a), "l"(b), "l"(d));
}
__device__ __forceinline__ void up2(u64 v, float& lo, float& hi) {
    asm("mov.b64 {%0,%1},%2;" : "=f"(lo), "=f"(hi) : "l"(v));
}

// ---------------- scratch ----------------
__device__ __align__(16) float g_Hdd[(size_t)NDRUG * DD];
__device__ __align__(16) float g_Hdp[(size_t)NDRUG * DD];
__device__ __align__(16) float g_Hpd[(size_t)NPROT * DD];
__device__ __align__(16) float g_Adrug[(size_t)NDRUG * DD];
__device__ __align__(16) float g_Aprot[(size_t)NPROT * DD];
// CSR
__device__ __align__(16) int g_cnt_dd[NDRUG];
__device__ __align__(16) int g_cnt_pd[NDRUG];
__device__ __align__(16) int g_cnt_dp[NPROT];
__device__ __align__(16) int g_off_dd[NDRUG + 4];
__device__ __align__(16) int g_off_pd[NDRUG + 4];
__device__ __align__(16) int g_off_dp[NPROT + 4];
__device__ __align__(16) int g_cur_dd[NDRUG + 4];
__device__ __align__(16) int g_cur_pd[NDRUG + 4];
__device__ __align__(16) int g_cur_dp[NPROT + 4];
__device__ int g_esrc_dd[EDD];
__device__ int g_esrc_pd[EPD];
__device__ int g_esrc_dp[EDP];
__device__ int g_part[NCH_TOT];
__device__ int g_pbase[NCH_TOT];
// transposed weights
__device__ __align__(16) float g_WtDD[DD * DD];
__device__ __align__(16) float g_WtDP[DD * DD];
__device__ __align__(16) float g_WtPD[DD * DD];
__device__ __align__(16) float g_WtDR[DD * 2 * DD];
__device__ __align__(16) float g_WtPR[DD * 2 * DD];

// ---------------- host-side stream/event resources (static init; no device mem) ----------------
struct GpuRes {
    cudaStream_t s1, s2;
    cudaEvent_t eFork, ePrep, eDD, ePD, eFill, eGPD, eEnd2;
    GpuRes() {
        cudaStreamCreateWithFlags(&s1, cudaStreamNonBlocking);
        cudaStreamCreateWithFlags(&s2, cudaStreamNonBlocking);
        cudaEventCreateWithFlags(&eFork, cudaEventDisableTiming);
        cudaEventCreateWithFlags(&ePrep, cudaEventDisableTiming);
        cudaEventCreateWithFlags(&eDD,   cudaEventDisableTiming);
        cudaEventCreateWithFlags(&ePD,   cudaEventDisableTiming);
        cudaEventCreateWithFlags(&eFill, cudaEventDisableTiming);
        cudaEventCreateWithFlags(&eGPD,  cudaEventDisableTiming);
        cudaEventCreateWithFlags(&eEnd2, cudaEventDisableTiming);
    }
};
static GpuRes g_res;

// ---------------- weight transpose ----------------
__global__ void prep_weights(const float* __restrict__ Wdd, const float* __restrict__ Wdp,
                             const float* __restrict__ Wpd, const float* __restrict__ Wdr,
                             const float* __restrict__ Wpr)
{
    int t = blockIdx.x * blockDim.x + threadIdx.x;
    int stride = gridDim.x * blockDim.x;
    for (int i = t; i < DD * DD; i += stride) {
        int c = i >> 7, k = i & 127;
        g_WtDD[k * DD + c] = Wdd[i];
        g_WtDP[k * DD + c] = Wdp[i];
        g_WtPD[k * DD + c] = Wpd[i];
    }
    for (int i = t; i < DD * 2 * DD; i += stride) {
        int c = i >> 8, col = i & 255;
        int k = col & 127, half = col >> 7;
        g_WtDR[k * 256 + half * 128 + c] = Wdr[i];
        g_WtPR[k * 256 + half * 128 + c] = Wpr[i];
    }
}

// ---------------- CSR build ----------------
__global__ void zero_counts() {
    int t = blockIdx.x * blockDim.x + threadIdx.x;
    int stride = gridDim.x * blockDim.x;
    for (int i = t; i < NDRUG; i += stride) { g_cnt_dd[i] = 0; g_cnt_pd[i] = 0; }
    for (int i = t; i < NPROT; i += stride) g_cnt_dp[i] = 0;
}

__global__ void count_all(const int* __restrict__ dd, const int* __restrict__ pd,
                          const int* __restrict__ dp) {
    int t = blockIdx.x * blockDim.x + threadIdx.x;
    if (t < EDD) atomicAdd(&g_cnt_dd[__ldg(&dd[t])], 1);
    else if (t < EDD + EPD) atomicAdd(&g_cnt_pd[__ldg(&pd[t - EDD])], 1);
    else if (t < EDD + EPD + EDP) atomicAdd(&g_cnt_dp[__ldg(&dp[t - EDD - EPD])], 1);
}

__device__ __forceinline__ void chunk_map(int b, const int*& cnt, int*& offs, int*& cur,
                                          int& base, int& n) {
    if (b < NCH_DD)              { cnt = g_cnt_dd; offs = g_off_dd; cur = g_cur_dd; base = b * CH; n = NDRUG; }
    else if (b < NCH_DD + NCH_PD){ cnt = g_cnt_pd; offs = g_off_pd; cur = g_cur_pd; base = (b - NCH_DD) * CH; n = NDRUG; }
    else                         { cnt = g_cnt_dp; offs = g_off_dp; cur = g_cur_dp; base = (b - NCH_DD - NCH_PD) * CH; n = NPROT; }
}

__global__ __launch_bounds__(1024) void chunk_sums() {
    const int* cnt; int* offs; int* cur; int base, n;
    chunk_map(blockIdx.x, cnt, offs, cur, base, n);
    int i0 = base + threadIdx.x * 4;
    int4 c = make_int4(0, 0, 0, 0);
    if (i0 < n) c = *reinterpret_cast<const int4*>(&cnt[i0]);
    int tot = c.x + c.y + c.z + c.w;
    __shared__ int ws[32];
    int lane = threadIdx.x & 31, wid = threadIdx.x >> 5;
#pragma unroll
    for (int o = 16; o; o >>= 1) tot += __shfl_xor_sync(0xFFFFFFFFu, tot, o);
    if (lane == 0) ws[wid] = tot;
    __syncthreads();
    if (wid == 0) {
        int v = ws[lane];
#pragma unroll
        for (int o = 16; o; o >>= 1) v += __shfl_xor_sync(0xFFFFFFFFu, v, o);
        if (lane == 0) g_part[blockIdx.x] = v;
    }
}

__global__ void scan_partials() {
    __shared__ int s[64];
    int t = threadIdx.x;
    int v = (t < NCH_TOT) ? g_part[t] : 0;
    s[t] = v;
    __syncthreads();
#pragma unroll
    for (int o = 1; o < 64; o <<= 1) {
        int add = (t >= o) ? s[t - o] : 0;
        __syncthreads();
        s[t] += add;
        __syncthreads();
    }
    if (t < NCH_TOT) {
        int excl = s[t] - v;
        int segoff = (t >= NCH_DD + NCH_PD) ? (EDD + EPD) : (t >= NCH_DD ? EDD : 0);
        g_pbase[t] = excl - segoff;
    }
    if (t == 0) {
        g_off_dd[NDRUG] = EDD;
        g_off_pd[NDRUG] = EPD;
        g_off_dp[NPROT] = EDP;
    }
}

__global__ __launch_bounds__(1024) void chunk_scan() {
    const int* cnt; int* offs; int* cur; int base, n;
    chunk_map(blockIdx.x, cnt, offs, cur, base, n);
    int carry = g_pbase[blockIdx.x];
    __shared__ int wsum[32];
    int tid = threadIdx.x, lane = tid & 31, wid = tid >> 5;
    int i0 = base + tid * 4;
    int4 c = make_int4(0, 0, 0, 0);
    if (i0 < n) c = *reinterpret_cast<const int4*>(&cnt[i0]);
    int tot = c.x + c.y + c.z + c.w;
    int incl = tot;
#pragma unroll
    for (int o = 1; o < 32; o <<= 1) {
        int v = __shfl_up_sync(0xFFFFFFFFu, incl, o);
        if (lane >= o) incl += v;
    }
    if (lane == 31) wsum[wid] = incl;
    __syncthreads();
    if (wid == 0) {
        int v = wsum[lane];
        int wincl = v;
#pragma unroll
        for (int o = 1; o < 32; o <<= 1) {
            int t2 = __shfl_up_sync(0xFFFFFFFFu, wincl, o);
            if (lane >= o) wincl += t2;
        }
        wsum[lane] = wincl - v;
    }
    __syncthreads();
    int excl = carry + wsum[wid] + incl - tot;
    if (i0 < n) {
        int e0 = excl, e1 = e0 + c.x, e2 = e1 + c.y, e3 = e2 + c.z;
        *reinterpret_cast<int4*>(&offs[i0]) = make_int4(e0, e1, e2, e3);
        *reinterpret_cast<int4*>(&cur[i0])  = make_int4(e0, e1, e2, e3);
    }
}

__global__ void fill_all(const int* __restrict__ dd_s, const int* __restrict__ dd_d,
                         const int* __restrict__ pd_s, const int* __restrict__ pd_d,
                         const int* __restrict__ dp_s, const int* __restrict__ dp_d) {
    int t = blockIdx.x * blockDim.x + threadIdx.x;
    if (t < EDD) {
        int slot = atomicAdd(&g_cur_dd[__ldg(&dd_d[t])], 1);
        g_esrc_dd[slot] = __ldg(&dd_s[t]);
    } else if (t < EDD + EPD) {
        int e = t - EDD;
        int slot = atomicAdd(&g_cur_pd[__ldg(&pd_d[e])], 1);
        g_esrc_pd[slot] = __ldg(&pd_s[e]);
    } else if (t < EDD + EPD + EDP) {
        int e = t - EDD - EPD;
        int slot = atomicAdd(&g_cur_dp[__ldg(&dp_d[e])], 1);
        g_esrc_dp[slot] = __ldg(&dp_s[e]);
    }
}

// ---------------- GEMM + ReLU (proven version) ----------------
__global__ __launch_bounds__(256, 3) void agg_gemm_relu(
    const float* __restrict__ X, const float* __restrict__ Wt,
    float* __restrict__ H, int N)
{
    __shared__ float xt[DD * XTS];

    int tid = threadIdx.x;
    int row0 = blockIdx.x * 64;
    for (int j = tid; j < 64 * 32; j += 256) {
        int r = j & 63, qg = j >> 6;
        int row = row0 + r;
        float4 v = make_float4(0.f, 0.f, 0.f, 0.f);
        if (row < N) v = *reinterpret_cast<const float4*>(&X[(size_t)row * DD + qg * 4]);
        xt[(qg * 4 + 0) * XTS + r] = v.x;
        xt[(qg * 4 + 1) * XTS + r] = v.y;
        xt[(qg * 4 + 2) * XTS + r] = v.z;
        xt[(qg * 4 + 3) * XTS + r] = v.w;
    }
    __syncthreads();

    int ct = tid & 31, rt = tid >> 5;
    int c0 = ct * 4, r0 = rt * 8;
    u64 acc[4][4];
#pragma unroll
    for (int rp = 0; rp < 4; rp++)
#pragma unroll
        for (int c = 0; c < 4; c++) acc[rp][c] = 0ull;

#pragma unroll 4
    for (int k = 0; k < DD; k++) {
        float4 w = __ldg(reinterpret_cast<const float4*>(&Wt[k * DD + c0]));
        float4 xa = *reinterpret_cast<const float4*>(&xt[k * XTS + r0]);
        float4 xb = *reinterpret_cast<const float4*>(&xt[k * XTS + r0 + 4]);
        u64 xp[4] = {pk2(xa.x, xa.y), pk2(xa.z, xa.w), pk2(xb.x, xb.y), pk2(xb.z, xb.w)};
        u64 wd[4] = {dp2(w.x), dp2(w.y), dp2(w.z), dp2(w.w)};
#pragma unroll
        for (int rp = 0; rp < 4; rp++)
#pragma unroll
            for (int c = 0; c < 4; c++) fma2(acc[rp][c], xp[rp], wd[c]);
    }

#pragma unroll
    for (int rp = 0; rp < 4; rp++) {
        float lo[4], hi[4];
#pragma unroll
        for (int c = 0; c < 4; c++) up2(acc[rp][c], lo[c], hi[c]);
        int ra = row0 + r0 + 2 * rp;
        if (ra < N) {
            float4 o = make_float4(fmaxf(lo[0], 0.f), fmaxf(lo[1], 0.f),
                                   fmaxf(lo[2], 0.f), fmaxf(lo[3], 0.f));
            *reinterpret_cast<float4*>(&H[(size_t)ra * DD + c0]) = o;
        }
        if (ra + 1 < N) {
            float4 o = make_float4(fmaxf(hi[0], 0.f), fmaxf(hi[1], 0.f),
                                   fmaxf(hi[2], 0.f), fmaxf(hi[3], 0.f));
            *reinterpret_cast<float4*>(&H[(size_t)(ra + 1) * DD + c0]) = o;
        }
    }
}

// ---------------- CSR gather (proven version) ----------------
__global__ __launch_bounds__(256) void edge_gather(
    const float* __restrict__ H, const int* __restrict__ esrc,
    const int* __restrict__ offs, float* __restrict__ A, int N, int mode)
{
    int w = (blockIdx.x * blockDim.x + threadIdx.x) >> 5;
    if (w >= N) return;
    int lane = threadIdx.x & 31;
    int beg = __ldg(&offs[w]), end = __ldg(&offs[w + 1]);
    float4 acc = make_float4(0.f, 0.f, 0.f, 0.f);
    int e = beg;
    for (; e + 4 <= end; e += 4) {
        int s0 = __ldg(&esrc[e]);
        int s1 = __ldg(&esrc[e + 1]);
        int s2 = __ldg(&esrc[e + 2]);
        int s3 = __ldg(&esrc[e + 3]);
        float4 v0 = __ldg(reinterpret_cast<const float4*>(&H[(size_t)s0 * DD + lane * 4]));
        float4 v1 = __ldg(reinterpret_cast<const float4*>(&H[(size_t)s1 * DD + lane * 4]));
        float4 v2 = __ldg(reinterpret_cast<const float4*>(&H[(size_t)s2 * DD + lane * 4]));
        float4 v3 = __ldg(reinterpret_cast<const float4*>(&H[(size_t)s3 * DD + lane * 4]));
        acc.x += (v0.x + v1.x) + (v2.x + v3.x);
        acc.y += (v0.y + v1.y) + (v2.y + v3.y);
        acc.z += (v0.z + v1.z) + (v2.z + v3.z);
        acc.w += (v0.w + v1.w) + (v2.w + v3.w);
    }
    for (; e < end; e++) {
        int s = __ldg(&esrc[e]);
        float4 v = __ldg(reinterpret_cast<const float4*>(&H[(size_t)s * DD + lane * 4]));
        acc.x += v.x; acc.y += v.y; acc.z += v.z; acc.w += v.w;
    }
    float inv = 1.0f / fmaxf((float)(end - beg), 1.0f);
    float4 o = make_float4(acc.x * inv, acc.y * inv, acc.z * inv, acc.w * inv);
    float* p = &A[(size_t)w * DD + lane * 4];
    if (mode) {
        float4 prev = *reinterpret_cast<const float4*>(p);
        o.x = 0.5f * (prev.x + o.x);
        o.y = 0.5f * (prev.y + o.y);
        o.z = 0.5f * (prev.z + o.z);
        o.w = 0.5f * (prev.w + o.w);
    }
    *reinterpret_cast<float4*>(p) = o;
}

// ---------------- fused node update (proven version) ----------------
__global__ __launch_bounds__(256, 2) void node_update(
    const float* __restrict__ X,
    const float* __restrict__ A,
    const float* __restrict__ Wt,
    const float* __restrict__ b,
    const float* __restrict__ g,
    const float* __restrict__ be,
    float* __restrict__ out, int N)
{
    __shared__ float xt[DD * XTS];
    __shared__ float at[DD * XTS];

    int tid = threadIdx.x;
    int row0 = blockIdx.x * 64;
    for (int j = tid; j < 64 * 32; j += 256) {
        int r = j & 63, qg = j >> 6;
        int row = row0 + r;
        float4 xv = make_float4(0.f, 0.f, 0.f, 0.f);
        float4 av = make_float4(0.f, 0.f, 0.f, 0.f);
        if (row < N) {
            xv = *reinterpret_cast<const float4*>(&X[(size_t)row * DD + qg * 4]);
            av = *reinterpret_cast<const float4*>(&A[(size_t)row * DD + qg * 4]);
        }
        xt[(qg * 4 + 0) * XTS + r] = xv.x;
        xt[(qg * 4 + 1) * XTS + r] = xv.y;
        xt[(qg * 4 + 2) * XTS + r] = xv.z;
        xt[(qg * 4 + 3) * XTS + r] = xv.w;
        at[(qg * 4 + 0) * XTS + r] = av.x;
        at[(qg * 4 + 1) * XTS + r] = av.y;
        at[(qg * 4 + 2) * XTS + r] = av.z;
        at[(qg * 4 + 3) * XTS + r] = av.w;
    }
    __syncthreads();

    int ct = tid & 31, rt = tid >> 5;
    int c0 = ct * 4, r0 = rt * 8;
    u64 acc[4][4];
#pragma unroll
    for (int rp = 0; rp < 4; rp++)
#pragma unroll
        for (int c = 0; c < 4; c++) acc[rp][c] = 0ull;

#pragma unroll 2
    for (int k = 0; k < DD; k++) {
        float4 w1 = __ldg(reinterpret_cast<const float4*>(&Wt[k * 256 + c0]));
        float4 w2 = __ldg(reinterpret_cast<const float4*>(&Wt[k * 256 + 128 + c0]));
        float4 xa = *reinterpret_cast<const float4*>(&xt[k * XTS + r0]);
        float4 xb = *reinterpret_cast<const float4*>(&xt[k * XTS + r0 + 4]);
        float4 aa = *reinterpret_cast<const float4*>(&at[k * XTS + r0]);
        float4 ab = *reinterpret_cast<const float4*>(&at[k * XTS + r0 + 4]);
        u64 xp[4] = {pk2(xa.x, xa.y), pk2(xa.z, xa.w), pk2(xb.x, xb.y), pk2(xb.z, xb.w)};
        u64 ap[4] = {pk2(aa.x, aa.y), pk2(aa.z, aa.w), pk2(ab.x, ab.y), pk2(ab.z, ab.w)};
        u64 w1d[4] = {dp2(w1.x), dp2(w1.y), dp2(w1.z), dp2(w1.w)};
        u64 w2d[4] = {dp2(w2.x), dp2(w2.y), dp2(w2.z), dp2(w2.w)};
#pragma unroll
        for (int rp = 0; rp < 4; rp++)
#pragma unroll
            for (int c = 0; c < 4; c++) {
                fma2(acc[rp][c], xp[rp], w1d[c]);
                fma2(acc[rp][c], ap[rp], w2d[c]);
            }
    }
    float4 bb = *reinterpret_cast<const float4*>(&b[c0]);
    __syncthreads();
    float* hs = xt;

#pragma unroll
    for (int rp = 0; rp < 4; rp++) {
        float lo[4], hi[4];
#pragma unroll
        for (int c = 0; c < 4; c++) up2(acc[rp][c], lo[c], hi[c]);
        int rla = r0 + 2 * rp;
        int ra = row0 + rla;
        float4 xra = make_float4(0.f, 0.f, 0.f, 0.f);
        float4 xrb = make_float4(0.f, 0.f, 0.f, 0.f);
        if (ra < N)     xra = *reinterpret_cast<const float4*>(&X[(size_t)ra * DD + c0]);
        if (ra + 1 < N) xrb = *reinterpret_cast<const float4*>(&X[(size_t)(ra + 1) * DD + c0]);
        float4 oa, ob;
        oa.x = fmaxf(lo[0] + bb.x, 0.f) + xra.x;
        oa.y = fmaxf(lo[1] + bb.y, 0.f) + xra.y;
        oa.z = fmaxf(lo[2] + bb.z, 0.f) + xra.z;
        oa.w = fmaxf(lo[3] + bb.w, 0.f) + xra.w;
        ob.x = fmaxf(hi[0] + bb.x, 0.f) + xrb.x;
        ob.y = fmaxf(hi[1] + bb.y, 0.f) + xrb.y;
        ob.z = fmaxf(hi[2] + bb.z, 0.f) + xrb.z;
        ob.w = fmaxf(hi[3] + bb.w, 0.f) + xrb.w;
        *reinterpret_cast<float4*>(&hs[rla * DD + c0]) = oa;
        *reinterpret_cast<float4*>(&hs[(rla + 1) * DD + c0]) = ob;
    }
    __syncthreads();

    int lane = tid & 31;
    float4 gg  = *reinterpret_cast<const float4*>(&g[lane * 4]);
    float4 bev = *reinterpret_cast<const float4*>(&be[lane * 4]);
    for (int r = 0; r < 8; r++) {
        int rl = rt * 8 + r;
        int row = row0 + rl;
        float4 v = *reinterpret_cast<const float4*>(&hs[rl * DD + lane * 4]);
        float s  = v.x + v.y + v.z + v.w;
        float s2 = v.x * v.x + v.y * v.y + v.z * v.z + v.w * v.w;
#pragma unroll
        for (int o_ = 16; o_; o_ >>= 1) {
            s  += __shfl_xor_sync(0xFFFFFFFFu, s, o_);
            s2 += __shfl_xor_sync(0xFFFFFFFFu, s2, o_);
        }
        float mu  = s * (1.0f / 128.0f);
        float var = s2 * (1.0f / 128.0f) - mu * mu;
        float rstd = rsqrtf(var + 1e-5f);
        if (row < N) {
            float4 o;
            o.x = (v.x - mu) * rstd * gg.x + bev.x;
            o.y = (v.y - mu) * rstd * gg.y + bev.y;
            o.z = (v.z - mu) * rstd * gg.z + bev.z;
            o.w = (v.w - mu) * rstd * gg.w + bev.w;
            *reinterpret_cast<float4*>(&out[(size_t)row * DD + lane * 4]) = o;
        }
    }
}

// ---------------- launch: three-branch DAG ----------------
extern "C" void kernel_launch(void* const* d_in, const int* in_sizes, int n_in,
                              void* d_out, int out_size)
{
    const float* x_drug  = (const float*)d_in[0];
    const float* x_prot  = (const float*)d_in[1];
    const float* Wagg_dd = (const float*)d_in[2];
    const float* Wagg_dp = (const float*)d_in[3];
    const float* Wagg_pd = (const float*)d_in[4];
    const float* W_drug  = (const float*)d_in[5];
    const float* b_drug  = (const float*)d_in[6];
    const float* W_prot  = (const float*)d_in[7];
    const float* b_prot  = (const float*)d_in[8];
    const float* g_drug  = (const float*)d_in[9];
    const float* be_drug = (const float*)d_in[10];
    const float* g_prot  = (const float*)d_in[11];
    const float* be_prot = (const float*)d_in[12];
    const int* dd_src = (const int*)d_in[13];
    const int* dd_dst = (const int*)d_in[14];
    const int* dp_src = (const int*)d_in[15];
    const int* dp_dst = (const int*)d_in[16];
    const int* pd_src = (const int*)d_in[17];
    const int* pd_dst = (const int*)d_in[18];
    float* out = (float*)d_out;

    float *Hdd, *Hdp, *Hpd, *Adrug, *Aprot;
    float *WtDD, *WtDP, *WtPD, *WtDR, *WtPR;
    int *off_dd, *off_pd, *off_dp, *esrc_dd, *esrc_pd, *esrc_dp;
    cudaGetSymbolAddress((void**)&Hdd, g_Hdd);
    cudaGetSymbolAddress((void**)&Hdp, g_Hdp);
    cudaGetSymbolAddress((void**)&Hpd, g_Hpd);
    cudaGetSymbolAddress((void**)&Adrug, g_Adrug);
    cudaGetSymbolAddress((void**)&Aprot, g_Aprot);
    cudaGetSymbolAddress((void**)&WtDD, g_WtDD);
    cudaGetSymbolAddress((void**)&WtDP, g_WtDP);
    cudaGetSymbolAddress((void**)&WtPD, g_WtPD);
    cudaGetSymbolAddress((void**)&WtDR, g_WtDR);
    cudaGetSymbolAddress((void**)&WtPR, g_WtPR);
    cudaGetSymbolAddress((void**)&off_dd, g_off_dd);
    cudaGetSymbolAddress((void**)&off_pd, g_off_pd);
    cudaGetSymbolAddress((void**)&off_dp, g_off_dp);
    cudaGetSymbolAddress((void**)&esrc_dd, g_esrc_dd);
    cudaGetSymbolAddress((void**)&esrc_pd, g_esrc_pd);
    cudaGetSymbolAddress((void**)&esrc_dp, g_esrc_dp);

    cudaStream_t s1 = g_res.s1;
    cudaStream_t s2 = g_res.s2;

    // ---- fork s1 off the main stream ----
    cudaEventRecord(g_res.eFork, 0);
    cudaStreamWaitEvent(s1, g_res.eFork, 0);

    // ---- s1: CSR build chain ----
    zero_counts<<<256, 256, 0, s1>>>();
    count_all<<<(EDD + EPD + EDP + 255) / 256, 256, 0, s1>>>(dd_dst, pd_dst, dp_dst);
    chunk_sums<<<NCH_TOT, 1024, 0, s1>>>();
    scan_partials<<<1, 64, 0, s1>>>();
    chunk_scan<<<NCH_TOT, 1024, 0, s1>>>();
    fill_all<<<(EDD + EPD + EDP + 255) / 256, 256, 0, s1>>>(dd_src, dd_dst, pd_src, pd_dst, dp_src, dp_dst);
    cudaEventRecord(g_res.eFill, s1);

    // ---- s0: weight prep + the two gather-feeding drug/prot aggs ----
    prep_weights<<<256, 256>>>(Wagg_dd, Wagg_dp, Wagg_pd, W_drug, W_prot);
    cudaEventRecord(g_res.ePrep, 0);
    agg_gemm_relu<<<(NDRUG + 63) / 64, 256>>>(x_drug, WtDD, Hdd, NDRUG);
    cudaEventRecord(g_res.eDD, 0);
    agg_gemm_relu<<<(NPROT + 63) / 64, 256>>>(x_prot, WtPD, Hpd, NPROT);
    cudaEventRecord(g_res.ePD, 0);

    // ---- s2: drug->prot branch (independent of node_drug) ----
    cudaStreamWaitEvent(s2, g_res.ePrep, 0);
    agg_gemm_relu<<<(NDRUG + 63) / 64, 256, 0, s2>>>(x_drug, WtDP, Hdp, NDRUG);
    cudaStreamWaitEvent(s2, g_res.eFill, 0);
    edge_gather<<<(NPROT * 32 + 255) / 256, 256, 0, s2>>>(Hdp, esrc_dp, off_dp, Aprot, NPROT, 0);
    node_update<<<(NPROT + 63) / 64, 256, 0, s2>>>(
        x_prot, Aprot, WtPR, b_prot, g_prot, be_prot,
        out + (size_t)NDRUG * DD, NPROT);
    cudaEventRecord(g_res.eEnd2, s2);

    // ---- s1: drug-side gathers ----
    cudaStreamWaitEvent(s1, g_res.eDD, 0);
    edge_gather<<<(NDRUG * 32 + 255) / 256, 256, 0, s1>>>(Hdd, esrc_dd, off_dd, Adrug, NDRUG, 0);
    cudaStreamWaitEvent(s1, g_res.ePD, 0);
    edge_gather<<<(NDRUG * 32 + 255) / 256, 256, 0, s1>>>(Hpd, esrc_pd, off_pd, Adrug, NDRUG, 1);
    cudaEventRecord(g_res.eGPD, s1);

    // ---- s0: drug node update (no longer behind agg_dp), then join ----
    cudaStreamWaitEvent(0, g_res.eGPD, 0);
    node_update<<<(NDRUG + 63) / 64, 256>>>(
        x_drug, Adrug, WtDR, b_drug, g_drug, be_drug, out, NDRUG);
    cudaStreamWaitEvent(0, g_res.eEnd2, 0);
}